// round 1
// baseline (speedup 1.0000x reference)
#include <cuda_runtime.h>
#include <cuda_bf16.h>
#include <math.h>

#define S_LEN   4096
#define HIDDEN  2048
#define NH      8
#define NKVH    4
#define DH      256
#define QR      6
#define KR      2
#define VR      2
#define WINDOW  1024
#define SOFTCAP 50.0f
#define SCALING 0.0625f     /* 256^-0.5 */
#define EPSV    1e-6f

/* ---------------- scratch (device globals; no allocation allowed) -------- */
__device__ float g_Aq[S_LEN * 48];
__device__ float g_Ak[S_LEN * 8];
__device__ float g_Av[S_LEN * 8];
__device__ float g_Bq[S_LEN * QR * DH];
__device__ float g_Bk[S_LEN * KR * DH];
__device__ float g_Bv[S_LEN * VR * DH];
__device__ float g_kA[S_LEN * NKVH * KR];
__device__ float g_kB[S_LEN * KR * DH];
__device__ float g_vA[S_LEN * NKVH * VR];
__device__ float g_vB[S_LEN * VR * DH];
__device__ float g_q [S_LEN * NH * DH];
__device__ float g_k [S_LEN * NKVH * DH];
__device__ float g_v [S_LEN * NKVH * DH];
__device__ float g_att[S_LEN * NH * DH];

/* ---------------- GEMM: C[M,N] = A[M,K] @ W[N,K]^T  (both row-major) -----
 * BM=BN=128, BK=8, 256 threads, 8x8 micro-tile per thread.
 * M is always a multiple of 128; N may be small (guarded). K multiple of 8. */
__global__ __launch_bounds__(256) void gemm_nt_kernel(
    const float* __restrict__ A, const float* __restrict__ W,
    float* __restrict__ C, int M, int N, int K)
{
    __shared__ float As[8][132];
    __shared__ float Ws[8][132];
    const int tid = threadIdx.x;
    const int m0 = blockIdx.y * 128;
    const int n0 = blockIdx.x * 128;

    const int lr = tid >> 1;          /* 0..127 row within tile        */
    const int lc = (tid & 1) * 4;     /* 0 or 4: col within 8-wide BK  */
    const int tm = (tid >> 4) * 8;    /* 0..120                        */
    const int tn = (tid & 15) * 8;

    float acc[8][8];
    #pragma unroll
    for (int i = 0; i < 8; i++)
        #pragma unroll
        for (int j = 0; j < 8; j++) acc[i][j] = 0.f;

    const float* Arow = A + (long)(m0 + lr) * K + lc;
    const bool wvalid = (n0 + lr) < N;
    const float* Wrow = W + (long)(wvalid ? (n0 + lr) : 0) * K + lc;

    for (int k0 = 0; k0 < K; k0 += 8) {
        float4 av = *(const float4*)(Arow + k0);
        float4 wv = wvalid ? *(const float4*)(Wrow + k0)
                           : make_float4(0.f, 0.f, 0.f, 0.f);
        __syncthreads();
        As[lc + 0][lr] = av.x; As[lc + 1][lr] = av.y;
        As[lc + 2][lr] = av.z; As[lc + 3][lr] = av.w;
        Ws[lc + 0][lr] = wv.x; Ws[lc + 1][lr] = wv.y;
        Ws[lc + 2][lr] = wv.z; Ws[lc + 3][lr] = wv.w;
        __syncthreads();
        #pragma unroll
        for (int kk = 0; kk < 8; kk++) {
            float a[8], b[8];
            #pragma unroll
            for (int i = 0; i < 8; i++) a[i] = As[kk][tm + i];
            #pragma unroll
            for (int j = 0; j < 8; j++) b[j] = Ws[kk][tn + j];
            #pragma unroll
            for (int i = 0; i < 8; i++)
                #pragma unroll
                for (int j = 0; j < 8; j++) acc[i][j] += a[i] * b[j];
        }
    }
    #pragma unroll
    for (int i = 0; i < 8; i++) {
        const long m = m0 + tm + i;
        #pragma unroll
        for (int j = 0; j < 8; j++) {
            const int n = n0 + tn + j;
            if (n < N) C[m * N + n] = acc[i][j];
        }
    }
}

/* ---------------- RoPE on B_q in place: [S, QR, D] ----------------------- */
__global__ void rope_q_kernel(const float* __restrict__ fc,
                              const float* __restrict__ fs)
{
    const int s = blockIdx.x;
    const int i = threadIdx.x;                 /* 0..127 = D/2 */
    const float c = fc[s * 128 + i], sn = fs[s * 128 + i];
    #pragma unroll
    for (int r = 0; r < QR; r++) {
        float* p = &g_Bq[(s * QR + r) * DH + 2 * i];
        const float x1 = p[0], x2 = p[1];
        p[0] = x1 * c - x2 * sn;
        p[1] = x1 * sn + x2 * c;
    }
}

/* ---------------- copy cache inputs into scratch caches ------------------ */
__global__ void copy_caches_kernel(const float* __restrict__ kcA,
                                   const float* __restrict__ kcB,
                                   const float* __restrict__ vcA,
                                   const float* __restrict__ vcB)
{
    const int i = blockIdx.x * 256 + threadIdx.x;
    if (i < S_LEN * 8)   { g_kA[i] = kcA[i]; g_vA[i] = vcA[i]; }
    if (i < S_LEN * 512) { g_kB[i] = kcB[i]; g_vB[i] = vcB[i]; }
}

/* -------- scatter A_k / A_v / RoPE(B_k) / B_v into caches at idx[s] ------ */
__global__ void scatter_kernel(const int* __restrict__ idx,
                               const float* __restrict__ fc,
                               const float* __restrict__ fs)
{
    const int s = blockIdx.x;
    const int tid = threadIdx.x;               /* 256 */
    const int t = idx[s];
    if (tid < 8) {
        g_kA[t * 8 + tid] = g_Ak[s * 8 + tid];
        g_vA[t * 8 + tid] = g_Av[s * 8 + tid];
    }
    const int r = tid >> 7, i = tid & 127;     /* KR=2 x 128 pairs */
    const float c = fc[s * 128 + i], sn = fs[s * 128 + i];
    const float* p = &g_Bk[(s * KR + r) * DH + 2 * i];
    const float x1 = p[0], x2 = p[1];
    g_kB[(t * KR + r) * DH + 2 * i]     = x1 * c - x2 * sn;
    g_kB[(t * KR + r) * DH + 2 * i + 1] = x1 * sn + x2 * c;
    g_vB[t * 512 + tid]       = g_Bv[s * 512 + tid];
    g_vB[t * 512 + 256 + tid] = g_Bv[s * 512 + 256 + tid];
}

/* -------- q[s,h,d] = RMSNorm( sum_r Aq*Bq / QR ) * (1+qw) * SCALING ------ */
__global__ void contract_q_kernel(const float* __restrict__ qw)
{
    const int s = blockIdx.x;
    const int d = threadIdx.x;                 /* 256 */
    __shared__ float a[48];
    __shared__ float wsum[8][8];
    if (d < 48) a[d] = g_Aq[s * 48 + d];
    __syncthreads();

    float bq[QR];
    #pragma unroll
    for (int r = 0; r < QR; r++) bq[r] = g_Bq[s * (QR * DH) + r * DH + d];

    float acc[NH];
    #pragma unroll
    for (int h = 0; h < NH; h++) {
        float v = 0.f;
        #pragma unroll
        for (int r = 0; r < QR; r++) v += a[h * QR + r] * bq[r];
        acc[h] = v * (1.0f / (float)QR);
    }
    const int lane = d & 31, warp = d >> 5;
    #pragma unroll
    for (int h = 0; h < NH; h++) {
        float v = acc[h] * acc[h];
        for (int o = 16; o > 0; o >>= 1) v += __shfl_xor_sync(0xffffffffu, v, o);
        if (lane == 0) wsum[h][warp] = v;
    }
    __syncthreads();
    const float w = 1.0f + qw[d];
    #pragma unroll
    for (int h = 0; h < NH; h++) {
        float tot = 0.f;
        #pragma unroll
        for (int i = 0; i < 8; i++) tot += wsum[h][i];
        const float rn = rsqrtf(tot * (1.0f / (float)DH) + EPSV);
        g_q[(s * NH + h) * DH + d] = acc[h] * rn * w * SCALING;
    }
}

/* -------- k[t,kh,d] = RMSNorm(kA*kB/KR)*(1+kw); v[t,kh,d] = vA*vB/VR ----- */
__global__ void contract_kv_kernel(const float* __restrict__ kw)
{
    const int t = blockIdx.x;
    const int d = threadIdx.x;                 /* 256 */
    __shared__ float a[16];                    /* [0:8)=kA, [8:16)=vA */
    __shared__ float wsum[4][8];
    if (d < 8)               a[d] = g_kA[t * 8 + d];
    else if (d < 16)         a[d] = g_vA[t * 8 + (d - 8)];
    __syncthreads();

    const float kb0 = g_kB[t * 512 + d],       kb1 = g_kB[t * 512 + 256 + d];
    const float vb0 = g_vB[t * 512 + d],       vb1 = g_vB[t * 512 + 256 + d];

    float kacc[NKVH], vacc[NKVH];
    #pragma unroll
    for (int kh = 0; kh < NKVH; kh++) {
        kacc[kh] = 0.5f * (a[kh * 2] * kb0 + a[kh * 2 + 1] * kb1);
        vacc[kh] = 0.5f * (a[8 + kh * 2] * vb0 + a[8 + kh * 2 + 1] * vb1);
    }
    const int lane = d & 31, warp = d >> 5;
    #pragma unroll
    for (int kh = 0; kh < NKVH; kh++) {
        float v = kacc[kh] * kacc[kh];
        for (int o = 16; o > 0; o >>= 1) v += __shfl_xor_sync(0xffffffffu, v, o);
        if (lane == 0) wsum[kh][warp] = v;
    }
    __syncthreads();
    const float w = 1.0f + kw[d];
    #pragma unroll
    for (int kh = 0; kh < NKVH; kh++) {
        float tot = 0.f;
        #pragma unroll
        for (int i = 0; i < 8; i++) tot += wsum[kh][i];
        const float rn = rsqrtf(tot * (1.0f / (float)DH) + EPSV);
        g_k[(t * NKVH + kh) * DH + d] = kacc[kh] * rn * w;
        g_v[(t * NKVH + kh) * DH + d] = vacc[kh];
    }
}

/* ---------------- sliding-window softcapped attention --------------------
 * One block per (32-query tile, head). Fixed softmax shift of SOFTCAP:
 * post-tanh scores are in [-50,50], so exp(s-50) needs no running max.   */
#define KS_STRIDE 257
#define VS_STRIDE 260
#define ATTN_SMEM_BYTES ((32 * KS_STRIDE * 2 + 32 * VS_STRIDE + 32 * 33 + 32 + 32) * 4)

__global__ __launch_bounds__(256) void attn_kernel(const int* __restrict__ idx)
{
    extern __shared__ float sm[];
    float* qs   = sm;                            /* 32 x 257 */
    float* ks   = qs + 32 * KS_STRIDE;           /* 32 x 257 */
    float* vs   = ks + 32 * KS_STRIDE;           /* 32 x 260 (16B-aligned rows) */
    float* ps   = vs + 32 * VS_STRIDE;           /* 32 x 33  */
    float* dsum = ps + 32 * 33;                  /* 32 */
    int*   qpos = (int*)(dsum + 32);             /* 32 */

    const int s0  = blockIdx.x * 32;
    const int h   = blockIdx.y;
    const int kvh = h >> 1;                      /* H/KVH = 2 */
    const int tid = threadIdx.x;

    for (int ii = tid; ii < 32 * 256; ii += 256) {
        const int qi = ii >> 8, d = ii & 255;
        qs[qi * KS_STRIDE + d] = g_q[((s0 + qi) * NH + h) * DH + d];
    }
    if (tid < 32) { dsum[tid] = 0.f; qpos[tid] = idx[s0 + tid]; }
    __syncthreads();

    float acc[32];
    #pragma unroll
    for (int i = 0; i < 32; i++) acc[i] = 0.f;

    const int w    = tid >> 5, j    = tid & 31;  /* QK mapping */
    const int qi2  = tid >> 3, dsub = tid & 7;   /* PV mapping */

    int tlo = s0 - (WINDOW - 1);
    if (tlo < 0) tlo = 0;
    tlo &= ~31;

    for (int tt = tlo; tt <= s0; tt += 32) {
        for (int ii = tid; ii < 32 * 256; ii += 256) {
            const int kj = ii >> 8, d = ii & 255;
            ks[kj * KS_STRIDE + d] = g_k[((tt + kj) * NKVH + kvh) * DH + d];
            vs[kj * VS_STRIDE + d] = g_v[((tt + kj) * NKVH + kvh) * DH + d];
        }
        __syncthreads();

        /* QK^T: warp w owns query rows 4w..4w+3; lane j = key index */
        {
            const float* krow = &ks[j * KS_STRIDE];
            const float* q0 = &qs[(w * 4 + 0) * KS_STRIDE];
            const float* q1 = q0 + KS_STRIDE;
            const float* q2 = q1 + KS_STRIDE;
            const float* q3 = q2 + KS_STRIDE;
            float d0 = 0.f, d1 = 0.f, d2 = 0.f, d3 = 0.f;
            #pragma unroll 8
            for (int d = 0; d < 256; d++) {
                const float kv = krow[d];
                d0 += q0[d] * kv; d1 += q1[d] * kv;
                d2 += q2[d] * kv; d3 += q3[d] * kv;
            }
            float dots[4] = {d0, d1, d2, d3};
            const int kp = tt + j;
            #pragma unroll
            for (int rr = 0; rr < 4; rr++) {
                const int qi = w * 4 + rr;
                const float sc = tanhf(dots[rr] * (1.0f / SOFTCAP)) * SOFTCAP;
                const int diff = qpos[qi] - kp;
                const float e = (diff >= 0 && diff < WINDOW)
                                    ? __expf(sc - SOFTCAP) : 0.f;
                ps[qi * 33 + j] = e;
                float rs = e;
                for (int o = 16; o > 0; o >>= 1)
                    rs += __shfl_xor_sync(0xffffffffu, rs, o);
                if (j == 0) dsum[qi] += rs;     /* rows exclusive per warp */
            }
        }
        __syncthreads();

        /* PV: thread (qi2, dsub) accumulates 32 dims (dsub*32 .. +31) */
        {
            const float* prow = &ps[qi2 * 33];
            #pragma unroll 4
            for (int jj = 0; jj < 32; jj++) {
                const float p = prow[jj];
                const float4* vrow =
                    (const float4*)&vs[jj * VS_STRIDE + dsub * 32];
                #pragma unroll
                for (int dd = 0; dd < 8; dd++) {
                    const float4 vv = vrow[dd];
                    acc[dd * 4 + 0] += p * vv.x;
                    acc[dd * 4 + 1] += p * vv.y;
                    acc[dd * 4 + 2] += p * vv.z;
                    acc[dd * 4 + 3] += p * vv.w;
                }
            }
        }
        __syncthreads();
    }

    const float inv = 1.0f / dsum[qi2];
    float* orow = &g_att[(long)(s0 + qi2) * (NH * DH) + h * DH + dsub * 32];
    #pragma unroll
    for (int dd = 0; dd < 8; dd++) {
        float4 ov;
        ov.x = acc[dd * 4 + 0] * inv; ov.y = acc[dd * 4 + 1] * inv;
        ov.z = acc[dd * 4 + 2] * inv; ov.w = acc[dd * 4 + 3] * inv;
        ((float4*)orow)[dd] = ov;
    }
}

/* ------------------------------- launch ---------------------------------- */
extern "C" void kernel_launch(void* const* d_in, const int* in_sizes, int n_in,
                              void* d_out, int out_size)
{
    const float* x   = (const float*)d_in[0];
    const float* fc  = (const float*)d_in[1];
    const float* fs  = (const float*)d_in[2];
    const float* WAq = (const float*)d_in[3];
    const float* WAk = (const float*)d_in[4];
    const float* WAv = (const float*)d_in[5];
    const float* WBq = (const float*)d_in[6];
    const float* WBk = (const float*)d_in[7];
    const float* WBv = (const float*)d_in[8];
    const float* Wo  = (const float*)d_in[9];
    const float* qw  = (const float*)d_in[10];
    const float* kw  = (const float*)d_in[11];
    const float* kcA = (const float*)d_in[12];
    const float* kcB = (const float*)d_in[13];
    const float* vcA = (const float*)d_in[14];
    const float* vcB = (const float*)d_in[15];
    const int*   idx = (const int*)d_in[16];
    float* out = (float*)d_out;

    float *pAq, *pAk, *pAv, *pBq, *pBk, *pBv, *pAtt;
    cudaGetSymbolAddress((void**)&pAq,  g_Aq);
    cudaGetSymbolAddress((void**)&pAk,  g_Ak);
    cudaGetSymbolAddress((void**)&pAv,  g_Av);
    cudaGetSymbolAddress((void**)&pBq,  g_Bq);
    cudaGetSymbolAddress((void**)&pBk,  g_Bk);
    cudaGetSymbolAddress((void**)&pBv,  g_Bv);
    cudaGetSymbolAddress((void**)&pAtt, g_att);

    cudaFuncSetAttribute(attn_kernel,
                         cudaFuncAttributeMaxDynamicSharedMemorySize,
                         ATTN_SMEM_BYTES);

    const dim3 blk(256);
    const int MB = S_LEN / 128;   /* 32 */

    /* projections */
    gemm_nt_kernel<<<dim3( 1, MB), blk>>>(x, WAq, pAq, S_LEN,   48, HIDDEN);
    gemm_nt_kernel<<<dim3( 1, MB), blk>>>(x, WAk, pAk, S_LEN,    8, HIDDEN);
    gemm_nt_kernel<<<dim3( 1, MB), blk>>>(x, WAv, pAv, S_LEN,    8, HIDDEN);
    gemm_nt_kernel<<<dim3(12, MB), blk>>>(x, WBq, pBq, S_LEN, 1536, HIDDEN);
    gemm_nt_kernel<<<dim3( 4, MB), blk>>>(x, WBk, pBk, S_LEN,  512, HIDDEN);
    gemm_nt_kernel<<<dim3( 4, MB), blk>>>(x, WBv, pBv, S_LEN,  512, HIDDEN);

    /* rope on B_q */
    rope_q_kernel<<<S_LEN, 128>>>(fc, fs);

    /* caches: copy inputs then scatter computed values (rope on B_k inline) */
    copy_caches_kernel<<<(S_LEN * 512 + 255) / 256, blk>>>(kcA, kcB, vcA, vcB);
    scatter_kernel<<<S_LEN, blk>>>(idx, fc, fs);

    /* tensor-product contraction + rmsnorm */
    contract_q_kernel <<<S_LEN, blk>>>(qw);
    contract_kv_kernel<<<S_LEN, blk>>>(kw);

    /* attention */
    attn_kernel<<<dim3(S_LEN / 32, NH), blk, ATTN_SMEM_BYTES>>>(idx);

    /* output projection */
    gemm_nt_kernel<<<dim3(16, MB), blk>>>(pAtt, Wo, out, S_LEN, HIDDEN, HIDDEN);
}

// round 6
// speedup vs baseline: 4.7264x; 4.7264x over previous
#include <cuda_runtime.h>
#include <cuda_bf16.h>
#include <math.h>
#include <stdint.h>

#define S_LEN   4096
#define HIDDEN  2048
#define NH      8
#define NKVH    4
#define DH      256
#define QR      6
#define KR      2
#define VR      2
#define WINDOW  1024
#define SOFTCAP 50.0f
#define SCALING 0.0625f     /* 256^-0.5 */
#define EPSV    1e-6f

/* ---------------- scratch (device globals; no allocation allowed) -------- */
__device__ float g_Aqkv[S_LEN * 128];
__device__ float g_Bq[S_LEN * QR * DH];
__device__ float g_Bk[S_LEN * KR * DH];
__device__ float g_Bv[S_LEN * VR * DH];
__device__ float g_kA[S_LEN * NKVH * KR];
__device__ float g_kB[S_LEN * KR * DH];
__device__ float g_vA[S_LEN * NKVH * VR];
__device__ float g_vB[S_LEN * VR * DH];
__device__ float g_q [S_LEN * NH * DH];
__device__ float g_k [S_LEN * NKVH * DH];
__device__ float g_v [S_LEN * NKVH * DH];
__device__ float g_att[S_LEN * NH * DH];

/* bf16 split operands */
__device__ __nv_bfloat16 g_xh [S_LEN * HIDDEN];
__device__ __nv_bfloat16 g_xl [S_LEN * HIDDEN];
__device__ __nv_bfloat16 g_WBq_h[1536 * HIDDEN];
__device__ __nv_bfloat16 g_WBq_l[1536 * HIDDEN];
__device__ __nv_bfloat16 g_WBk_h[ 512 * HIDDEN];
__device__ __nv_bfloat16 g_WBk_l[ 512 * HIDDEN];
__device__ __nv_bfloat16 g_WBv_h[ 512 * HIDDEN];
__device__ __nv_bfloat16 g_WBv_l[ 512 * HIDDEN];
__device__ __nv_bfloat16 g_Wo_h[HIDDEN * HIDDEN];
__device__ __nv_bfloat16 g_Wo_l[HIDDEN * HIDDEN];
__device__ __nv_bfloat16 g_WA_h[128 * HIDDEN];
__device__ __nv_bfloat16 g_WA_l[128 * HIDDEN];
__device__ __nv_bfloat16 g_atth[S_LEN * HIDDEN];
__device__ __nv_bfloat16 g_attl[S_LEN * HIDDEN];

/* ---------------- fp32 -> (bf16 hi, bf16 lo) split ----------------------- */
__global__ void split_kernel(const float* __restrict__ in,
                             __nv_bfloat16* __restrict__ hi,
                             __nv_bfloat16* __restrict__ lo, int n)
{
    for (int i = blockIdx.x * 256 + threadIdx.x; i < n; i += gridDim.x * 256) {
        const float a = in[i];
        const __nv_bfloat16 h = __float2bfloat16(a);
        hi[i] = h;
        lo[i] = __float2bfloat16(a - __bfloat162float(h));
    }
}

/* ----- concat W_A_q(48) | W_A_k(8) | W_A_v(8) | zeros -> [128][2048] ----- */
__global__ void wacat_kernel(const float* __restrict__ WAq,
                             const float* __restrict__ WAk,
                             const float* __restrict__ WAv)
{
    for (int i = blockIdx.x * 256 + threadIdx.x; i < 128 * HIDDEN;
         i += gridDim.x * 256) {
        const int row = i >> 11, col = i & 2047;
        float v = 0.f;
        if (row < 48)       v = WAq[row * HIDDEN + col];
        else if (row < 56)  v = WAk[(row - 48) * HIDDEN + col];
        else if (row < 64)  v = WAv[(row - 56) * HIDDEN + col];
        const __nv_bfloat16 h = __float2bfloat16(v);
        g_WA_h[i] = h;
        g_WA_l[i] = __float2bfloat16(v - __bfloat162float(h));
    }
}

/* ---------------- HMMA split-bf16 GEMM: C[M,N] = A @ W^T ------------------
 * A[M,K], W[N,K], both row-major, split into hi/lo bf16.
 * BM=BN=128, BK=16, 256 threads = 8 warps (2x4 of 64x32 warp tiles).
 * Requires M%128==0, N%128==0, K%16==0.                                   */
#define LDSM4(d, a) \
    asm volatile("ldmatrix.sync.aligned.m8n8.x4.shared.b16 {%0,%1,%2,%3}, [%4];" \
        : "=r"(d[0]), "=r"(d[1]), "=r"(d[2]), "=r"(d[3]) : "r"(a))

#define MMA16816(c, a, b0, b1) \
    asm volatile("mma.sync.aligned.m16n8k16.row.col.f32.bf16.bf16.f32 " \
        "{%0,%1,%2,%3}, {%4,%5,%6,%7}, {%8,%9}, {%0,%1,%2,%3};" \
        : "+f"(c[0]), "+f"(c[1]), "+f"(c[2]), "+f"(c[3]) \
        : "r"(a[0]), "r"(a[1]), "r"(a[2]), "r"(a[3]), "r"(b0), "r"(b1))

__global__ __launch_bounds__(256) void hgemm_kernel(
    const __nv_bfloat16* __restrict__ Ah, const __nv_bfloat16* __restrict__ Al,
    const __nv_bfloat16* __restrict__ Wh, const __nv_bfloat16* __restrict__ Wl,
    float* __restrict__ C, int N, int K)
{
    /* parts: 0=Ah 1=Al 2=Wh 3=Wl ; 128 rows x 24 bf16 (16 data + 8 pad) */
    __shared__ __align__(16) __nv_bfloat16 sm[2][4][128 * 24];
    const int tid  = threadIdx.x;
    const int m0   = blockIdx.y * 128, n0 = blockIdx.x * 128;
    const int warp = tid >> 5, lane = tid & 31;
    const int wm   = (warp & 1) * 64, wn = (warp >> 1) * 32;

    /* gmem->smem mapping: row = tid>>1 (0..127), 8-elem segment = tid&1 */
    const int ldr = tid >> 1, lds8 = (tid & 1) * 8;
    const __nv_bfloat16* gAh = Ah + (size_t)(m0 + ldr) * K + lds8;
    const __nv_bfloat16* gAl = Al + (size_t)(m0 + ldr) * K + lds8;
    const __nv_bfloat16* gWh = Wh + (size_t)(n0 + ldr) * K + lds8;
    const __nv_bfloat16* gWl = Wl + (size_t)(n0 + ldr) * K + lds8;
    const int stoff = ldr * 24 + lds8;

    /* ldmatrix per-lane addressing (conflict-free with 48B row stride) */
    const int r8   = lane & 7, tq = lane >> 3;
    const int lrow = (tq & 1) * 8 + r8;
    const int lcol = (tq >> 1) * 8;
    const uint32_t smBase = (uint32_t)__cvta_generic_to_shared(&sm[0][0][0]);
    const uint32_t aoff = ((wm + lrow) * 24 + lcol) * 2;
    const uint32_t boff = ((wn + lrow) * 24 + lcol) * 2;

    float c[4][4][4];
    #pragma unroll
    for (int mt = 0; mt < 4; mt++)
        #pragma unroll
        for (int nt = 0; nt < 4; nt++)
            #pragma unroll
            for (int f = 0; f < 4; f++) c[mt][nt][f] = 0.f;

    /* preload k-step 0 */
    {
        uint4 va = *(const uint4*)gAh;
        uint4 vb = *(const uint4*)gAl;
        uint4 vc = *(const uint4*)gWh;
        uint4 vd = *(const uint4*)gWl;
        *(uint4*)&sm[0][0][stoff] = va;
        *(uint4*)&sm[0][1][stoff] = vb;
        *(uint4*)&sm[0][2][stoff] = vc;
        *(uint4*)&sm[0][3][stoff] = vd;
    }

    const int NS = K >> 4;
    for (int ks = 0; ks < NS; ks++) {
        __syncthreads();
        const int buf = ks & 1;
        if (ks + 1 < NS) {
            const int ko = (ks + 1) << 4;
            uint4 va = *(const uint4*)(gAh + ko);
            uint4 vb = *(const uint4*)(gAl + ko);
            uint4 vc = *(const uint4*)(gWh + ko);
            uint4 vd = *(const uint4*)(gWl + ko);
            const int nb = buf ^ 1;
            *(uint4*)&sm[nb][0][stoff] = va;
            *(uint4*)&sm[nb][1][stoff] = vb;
            *(uint4*)&sm[nb][2][stoff] = vc;
            *(uint4*)&sm[nb][3][stoff] = vd;
        }
        const uint32_t base = smBase + (uint32_t)buf * (4 * 3072 * 2);
        uint32_t ah[4][4], al[4][4], bh[2][4], bl[2][4];
        #pragma unroll
        for (int mt = 0; mt < 4; mt++) {
            LDSM4(ah[mt], base + 0 * 6144 + aoff + mt * 768);
            LDSM4(al[mt], base + 1 * 6144 + aoff + mt * 768);
        }
        #pragma unroll
        for (int p = 0; p < 2; p++) {
            LDSM4(bh[p], base + 2 * 6144 + boff + p * 768);
            LDSM4(bl[p], base + 3 * 6144 + boff + p * 768);
        }
        #pragma unroll
        for (int mt = 0; mt < 4; mt++)
            #pragma unroll
            for (int nt = 0; nt < 4; nt++) {
                const int p = nt >> 1, q = nt & 1;
                MMA16816(c[mt][nt], ah[mt], bh[p][q], bh[p][q + 2]);
                MMA16816(c[mt][nt], ah[mt], bl[p][q], bl[p][q + 2]);
                MMA16816(c[mt][nt], al[mt], bh[p][q], bh[p][q + 2]);
            }
    }

    const int gid = lane >> 2, tg = lane & 3;
    #pragma unroll
    for (int mt = 0; mt < 4; mt++)
        #pragma unroll
        for (int nt = 0; nt < 4; nt++) {
            const int row = m0 + wm + mt * 16 + gid;
            const int col = n0 + wn + nt * 8 + tg * 2;
            float2 v0 = make_float2(c[mt][nt][0], c[mt][nt][1]);
            float2 v1 = make_float2(c[mt][nt][2], c[mt][nt][3]);
            *(float2*)&C[(size_t)row * N + col]       = v0;
            *(float2*)&C[(size_t)(row + 8) * N + col] = v1;
        }
}

/* ---------------- RoPE on B_q in place: [S, QR, D] ----------------------- */
__global__ void rope_q_kernel(const float* __restrict__ fc,
                              const float* __restrict__ fs)
{
    const int s = blockIdx.x;
    const int i = threadIdx.x;                 /* 0..127 = D/2 */
    const float c = fc[s * 128 + i], sn = fs[s * 128 + i];
    #pragma unroll
    for (int r = 0; r < QR; r++) {
        float* p = &g_Bq[(s * QR + r) * DH + 2 * i];
        const float x1 = p[0], x2 = p[1];
        p[0] = x1 * c - x2 * sn;
        p[1] = x1 * sn + x2 * c;
    }
}

/* ---------------- copy cache inputs into scratch caches ------------------ */
__global__ void copy_caches_kernel(const float* __restrict__ kcA,
                                   const float* __restrict__ kcB,
                                   const float* __restrict__ vcA,
                                   const float* __restrict__ vcB)
{
    const int i = blockIdx.x * 256 + threadIdx.x;
    if (i < S_LEN * 8)   { g_kA[i] = kcA[i]; g_vA[i] = vcA[i]; }
    if (i < S_LEN * 512) { g_kB[i] = kcB[i]; g_vB[i] = vcB[i]; }
}

/* -------- scatter A_k / A_v / RoPE(B_k) / B_v into caches at idx[s] ------ */
__global__ void scatter_kernel(const int* __restrict__ idx,
                               const float* __restrict__ fc,
                               const float* __restrict__ fs)
{
    const int s = blockIdx.x;
    const int tid = threadIdx.x;               /* 256 */
    const int t = idx[s];
    if (tid < 8) {
        g_kA[t * 8 + tid] = g_Aqkv[s * 128 + 48 + tid];
        g_vA[t * 8 + tid] = g_Aqkv[s * 128 + 56 + tid];
    }
    const int r = tid >> 7, i = tid & 127;     /* KR=2 x 128 pairs */
    const float c = fc[s * 128 + i], sn = fs[s * 128 + i];
    const float* p = &g_Bk[(s * KR + r) * DH + 2 * i];
    const float x1 = p[0], x2 = p[1];
    g_kB[(t * KR + r) * DH + 2 * i]     = x1 * c - x2 * sn;
    g_kB[(t * KR + r) * DH + 2 * i + 1] = x1 * sn + x2 * c;
    g_vB[t * 512 + tid]       = g_Bv[s * 512 + tid];
    g_vB[t * 512 + 256 + tid] = g_Bv[s * 512 + 256 + tid];
}

/* -------- q[s,h,d] = RMSNorm( sum_r Aq*Bq / QR ) * (1+qw) * SCALING ------ */
__global__ void contract_q_kernel(const float* __restrict__ qw)
{
    const int s = blockIdx.x;
    const int d = threadIdx.x;                 /* 256 */
    __shared__ float a[48];
    __shared__ float wsum[8][8];
    if (d < 48) a[d] = g_Aqkv[s * 128 + d];
    __syncthreads();

    float bq[QR];
    #pragma unroll
    for (int r = 0; r < QR; r++) bq[r] = g_Bq[s * (QR * DH) + r * DH + d];

    float acc[NH];
    #pragma unroll
    for (int h = 0; h < NH; h++) {
        float v = 0.f;
        #pragma unroll
        for (int r = 0; r < QR; r++) v += a[h * QR + r] * bq[r];
        acc[h] = v * (1.0f / (float)QR);
    }
    const int lane = d & 31, warp = d >> 5;
    #pragma unroll
    for (int h = 0; h < NH; h++) {
        float v = acc[h] * acc[h];
        for (int o = 16; o > 0; o >>= 1) v += __shfl_xor_sync(0xffffffffu, v, o);
        if (lane == 0) wsum[h][warp] = v;
    }
    __syncthreads();
    const float w = 1.0f + qw[d];
    #pragma unroll
    for (int h = 0; h < NH; h++) {
        float tot = 0.f;
        #pragma unroll
        for (int i = 0; i < 8; i++) tot += wsum[h][i];
        const float rn = rsqrtf(tot * (1.0f / (float)DH) + EPSV);
        g_q[(s * NH + h) * DH + d] = acc[h] * rn * w * SCALING;
    }
}

/* -------- k[t,kh,d] = RMSNorm(kA*kB/KR)*(1+kw); v[t,kh,d] = vA*vB/VR ----- */
__global__ void contract_kv_kernel(const float* __restrict__ kw)
{
    const int t = blockIdx.x;
    const int d = threadIdx.x;                 /* 256 */
    __shared__ float a[16];
    __shared__ float wsum[4][8];
    if (d < 8)               a[d] = g_kA[t * 8 + d];
    else if (d < 16)         a[d] = g_vA[t * 8 + (d - 8)];
    __syncthreads();

    const float kb0 = g_kB[t * 512 + d],       kb1 = g_kB[t * 512 + 256 + d];
    const float vb0 = g_vB[t * 512 + d],       vb1 = g_vB[t * 512 + 256 + d];

    float kacc[NKVH], vacc[NKVH];
    #pragma unroll
    for (int kh = 0; kh < NKVH; kh++) {
        kacc[kh] = 0.5f * (a[kh * 2] * kb0 + a[kh * 2 + 1] * kb1);
        vacc[kh] = 0.5f * (a[8 + kh * 2] * vb0 + a[8 + kh * 2 + 1] * vb1);
    }
    const int lane = d & 31, warp = d >> 5;
    #pragma unroll
    for (int kh = 0; kh < NKVH; kh++) {
        float v = kacc[kh] * kacc[kh];
        for (int o = 16; o > 0; o >>= 1) v += __shfl_xor_sync(0xffffffffu, v, o);
        if (lane == 0) wsum[kh][warp] = v;
    }
    __syncthreads();
    const float w = 1.0f + kw[d];
    #pragma unroll
    for (int kh = 0; kh < NKVH; kh++) {
        float tot = 0.f;
        #pragma unroll
        for (int i = 0; i < 8; i++) tot += wsum[kh][i];
        const float rn = rsqrtf(tot * (1.0f / (float)DH) + EPSV);
        g_k[(t * NKVH + kh) * DH + d] = kacc[kh] * rn * w;
        g_v[(t * NKVH + kh) * DH + d] = vacc[kh];
    }
}

/* ---------------- sliding-window softcapped attention --------------------
 * Block = 64 queries x 1 head; key tiles of 64.
 * 256 thr as 16x16; QK micro-tile 4x4 via transposed q/k smem (float4 frags);
 * PV micro-tile 4q x 16d. Fixed softmax shift exp(s-50): post-tanh scores
 * are bounded by +-50, so no running max is needed.                        */
#define AT_TSTR 68
#define AT_VSTR 260
#define ATTN_SMEM_BYTES ((256*AT_TSTR*2 + 64*AT_VSTR + 64*AT_TSTR + 64 + 64) * 4)

__global__ __launch_bounds__(256) void attn_kernel(const int* __restrict__ idx)
{
    extern __shared__ float smf[];
    float* qT   = smf;                       /* [256][68]  q transposed */
    float* kT   = qT + 256 * AT_TSTR;        /* [256][68]  k transposed */
    float* vR   = kT + 256 * AT_TSTR;        /* [64][260]  v row-major  */
    float* pS   = vR + 64 * AT_VSTR;         /* [64][68]   probs        */
    float* dsum = pS + 64 * AT_TSTR;         /* [64] */
    int*   qpos = (int*)(dsum + 64);         /* [64] */

    const int s0  = blockIdx.x * 64;
    const int h   = blockIdx.y;
    const int kvh = h >> 1;
    const int tid = threadIdx.x;
    const int tx = tid & 15, ty = tid >> 4;
    const int tx4 = tx * 4, ty4 = ty * 4;

    /* q -> transposed smem (d-major) */
    {
        const int qi = tid & 63, dg = (tid >> 6) * 4;
        const float* qb = &g_q[((size_t)(s0 + qi) * NH + h) * DH];
        #pragma unroll
        for (int it = 0; it < 16; it++) {
            const int d0 = dg + it * 16;
            const float4 v = *(const float4*)(qb + d0);
            qT[(d0 + 0) * AT_TSTR + qi] = v.x;
            qT[(d0 + 1) * AT_TSTR + qi] = v.y;
            qT[(d0 + 2) * AT_TSTR + qi] = v.z;
            qT[(d0 + 3) * AT_TSTR + qi] = v.w;
        }
    }
    if (tid < 64) { dsum[tid] = 0.f; qpos[tid] = idx[s0 + tid]; }

    float o[4][4][4];
    #pragma unroll
    for (int i = 0; i < 4; i++)
        #pragma unroll
        for (int b = 0; b < 4; b++)
            #pragma unroll
            for (int c = 0; c < 4; c++) o[i][b][c] = 0.f;

    int tlo = s0 - (WINDOW - 1);
    if (tlo < 0) tlo = 0;
    tlo &= ~63;

    for (int t0 = tlo; t0 < s0 + 64; t0 += 64) {
        __syncthreads();
        /* k -> transposed smem */
        {
            const int j = tid & 63, dg = (tid >> 6) * 4;
            const float* kb = &g_k[((size_t)(t0 + j) * NKVH + kvh) * DH];
            #pragma unroll
            for (int it = 0; it < 16; it++) {
                const int d0 = dg + it * 16;
                const float4 v = *(const float4*)(kb + d0);
                kT[(d0 + 0) * AT_TSTR + j] = v.x;
                kT[(d0 + 1) * AT_TSTR + j] = v.y;
                kT[(d0 + 2) * AT_TSTR + j] = v.z;
                kT[(d0 + 3) * AT_TSTR + j] = v.w;
            }
        }
        /* v -> row-major smem (coalesced) */
        #pragma unroll
        for (int it = 0; it < 16; it++) {
            const int ii = tid + it * 256;
            const int j = ii >> 6, dq = (ii & 63) << 2;
            const float4 v =
                *(const float4*)&g_v[((size_t)(t0 + j) * NKVH + kvh) * DH + dq];
            *(float4*)&vR[j * AT_VSTR + dq] = v;
        }
        __syncthreads();

        /* QK^T 64x64, 4x4 per thread */
        float sc[4][4];
        #pragma unroll
        for (int i = 0; i < 4; i++)
            #pragma unroll
            for (int j = 0; j < 4; j++) sc[i][j] = 0.f;
        #pragma unroll 4
        for (int d = 0; d < 256; d++) {
            const float4 qv = *(const float4*)&qT[d * AT_TSTR + ty4];
            const float4 kv = *(const float4*)&kT[d * AT_TSTR + tx4];
            sc[0][0] += qv.x * kv.x; sc[0][1] += qv.x * kv.y;
            sc[0][2] += qv.x * kv.z; sc[0][3] += qv.x * kv.w;
            sc[1][0] += qv.y * kv.x; sc[1][1] += qv.y * kv.y;
            sc[1][2] += qv.y * kv.z; sc[1][3] += qv.y * kv.w;
            sc[2][0] += qv.z * kv.x; sc[2][1] += qv.z * kv.y;
            sc[2][2] += qv.z * kv.z; sc[2][3] += qv.z * kv.w;
            sc[3][0] += qv.w * kv.x; sc[3][1] += qv.w * kv.y;
            sc[3][2] += qv.w * kv.z; sc[3][3] += qv.w * kv.w;
        }
        /* softcap + window mask + exp(s - 50) */
        #pragma unroll
        for (int i = 0; i < 4; i++) {
            const int qp = qpos[ty4 + i];
            #pragma unroll
            for (int j = 0; j < 4; j++) {
                const int kp = t0 + tx4 + j;
                const float e = tanhf(sc[i][j] * (1.0f / SOFTCAP)) * SOFTCAP;
                const int diff = qp - kp;
                const float p = (diff >= 0 && diff < WINDOW)
                                    ? __expf(e - SOFTCAP) : 0.f;
                pS[(ty4 + i) * AT_TSTR + tx4 + j] = p;
            }
        }
        __syncthreads();
        if (tid < 64) {
            float s = 0.f;
            #pragma unroll 8
            for (int c = 0; c < 64; c++) s += pS[tid * AT_TSTR + c];
            dsum[tid] += s;
        }
        /* PV: 4q x 16d per thread (d in 4 blocks of 64) */
        #pragma unroll 2
        for (int j = 0; j < 64; j++) {
            const float p0 = pS[(ty4 + 0) * AT_TSTR + j];
            const float p1 = pS[(ty4 + 1) * AT_TSTR + j];
            const float p2 = pS[(ty4 + 2) * AT_TSTR + j];
            const float p3 = pS[(ty4 + 3) * AT_TSTR + j];
            #pragma unroll
            for (int b = 0; b < 4; b++) {
                const float4 vv =
                    *(const float4*)&vR[j * AT_VSTR + b * 64 + tx4];
                o[0][b][0] += p0 * vv.x; o[0][b][1] += p0 * vv.y;
                o[0][b][2] += p0 * vv.z; o[0][b][3] += p0 * vv.w;
                o[1][b][0] += p1 * vv.x; o[1][b][1] += p1 * vv.y;
                o[1][b][2] += p1 * vv.z; o[1][b][3] += p1 * vv.w;
                o[2][b][0] += p2 * vv.x; o[2][b][1] += p2 * vv.y;
                o[2][b][2] += p2 * vv.z; o[2][b][3] += p2 * vv.w;
                o[3][b][0] += p3 * vv.x; o[3][b][1] += p3 * vv.y;
                o[3][b][2] += p3 * vv.z; o[3][b][3] += p3 * vv.w;
            }
        }
    }
    __syncthreads();
    #pragma unroll
    for (int i = 0; i < 4; i++) {
        const float inv = 1.0f / dsum[ty4 + i];
        float* ob = &g_att[(size_t)(s0 + ty4 + i) * (NH * DH) + h * DH];
        #pragma unroll
        for (int b = 0; b < 4; b++) {
            float4 v;
            v.x = o[i][b][0] * inv; v.y = o[i][b][1] * inv;
            v.z = o[i][b][2] * inv; v.w = o[i][b][3] * inv;
            *(float4*)&ob[b * 64 + tx4] = v;
        }
    }
}

/* ------------------------------- launch ---------------------------------- */
extern "C" void kernel_launch(void* const* d_in, const int* in_sizes, int n_in,
                              void* d_out, int out_size)
{
    const float* x   = (const float*)d_in[0];
    const float* fc  = (const float*)d_in[1];
    const float* fs  = (const float*)d_in[2];
    const float* WAq = (const float*)d_in[3];
    const float* WAk = (const float*)d_in[4];
    const float* WAv = (const float*)d_in[5];
    const float* WBq = (const float*)d_in[6];
    const float* WBk = (const float*)d_in[7];
    const float* WBv = (const float*)d_in[8];
    const float* Wo  = (const float*)d_in[9];
    const float* qw  = (const float*)d_in[10];
    const float* kw  = (const float*)d_in[11];
    const float* kcA = (const float*)d_in[12];
    const float* kcB = (const float*)d_in[13];
    const float* vcA = (const float*)d_in[14];
    const float* vcB = (const float*)d_in[15];
    const int*   idx = (const int*)d_in[16];
    float* out = (float*)d_out;

    float *pAqkv, *pBq, *pBk, *pBv, *pAtt;
    __nv_bfloat16 *pxh, *pxl, *pWBqh, *pWBql, *pWBkh, *pWBkl, *pWBvh, *pWBvl;
    __nv_bfloat16 *pWoh, *pWol, *pWAh, *pWAl, *patth, *pattl;
    cudaGetSymbolAddress((void**)&pAqkv, g_Aqkv);
    cudaGetSymbolAddress((void**)&pBq,   g_Bq);
    cudaGetSymbolAddress((void**)&pBk,   g_Bk);
    cudaGetSymbolAddress((void**)&pBv,   g_Bv);
    cudaGetSymbolAddress((void**)&pAtt,  g_att);
    cudaGetSymbolAddress((void**)&pxh,   g_xh);
    cudaGetSymbolAddress((void**)&pxl,   g_xl);
    cudaGetSymbolAddress((void**)&pWBqh, g_WBq_h);
    cudaGetSymbolAddress((void**)&pWBql, g_WBq_l);
    cudaGetSymbolAddress((void**)&pWBkh, g_WBk_h);
    cudaGetSymbolAddress((void**)&pWBkl, g_WBk_l);
    cudaGetSymbolAddress((void**)&pWBvh, g_WBv_h);
    cudaGetSymbolAddress((void**)&pWBvl, g_WBv_l);
    cudaGetSymbolAddress((void**)&pWoh,  g_Wo_h);
    cudaGetSymbolAddress((void**)&pWol,  g_Wo_l);
    cudaGetSymbolAddress((void**)&pWAh,  g_WA_h);
    cudaGetSymbolAddress((void**)&pWAl,  g_WA_l);
    cudaGetSymbolAddress((void**)&patth, g_atth);
    cudaGetSymbolAddress((void**)&pattl, g_attl);

    cudaFuncSetAttribute(attn_kernel,
                         cudaFuncAttributeMaxDynamicSharedMemorySize,
                         ATTN_SMEM_BYTES);

    const dim3 blk(256);
    const int MB = S_LEN / 128;   /* 32 */

    /* split conversions */
    split_kernel<<<2048, blk>>>(x,   pxh,   pxl,   S_LEN * HIDDEN);
    split_kernel<<<2048, blk>>>(WBq, pWBqh, pWBql, 1536 * HIDDEN);
    split_kernel<<<1024, blk>>>(WBk, pWBkh, pWBkl,  512 * HIDDEN);
    split_kernel<<<1024, blk>>>(WBv, pWBvh, pWBvl,  512 * HIDDEN);
    split_kernel<<<2048, blk>>>(Wo,  pWoh,  pWol,  HIDDEN * HIDDEN);
    wacat_kernel<<<512, blk>>>(WAq, WAk, WAv);

    /* projections (tensor cores) */
    hgemm_kernel<<<dim3( 1, MB), blk>>>(pxh, pxl, pWAh,  pWAl,  pAqkv, 128, HIDDEN);
    hgemm_kernel<<<dim3(12, MB), blk>>>(pxh, pxl, pWBqh, pWBql, pBq, 1536, HIDDEN);
    hgemm_kernel<<<dim3( 4, MB), blk>>>(pxh, pxl, pWBkh, pWBkl, pBk,  512, HIDDEN);
    hgemm_kernel<<<dim3( 4, MB), blk>>>(pxh, pxl, pWBvh, pWBvl, pBv,  512, HIDDEN);

    /* rope on B_q */
    rope_q_kernel<<<S_LEN, 128>>>(fc, fs);

    /* caches */
    copy_caches_kernel<<<(S_LEN * 512 + 255) / 256, blk>>>(kcA, kcB, vcA, vcB);
    scatter_kernel<<<S_LEN, blk>>>(idx, fc, fs);

    /* tensor-product contraction + rmsnorm */
    contract_q_kernel <<<S_LEN, blk>>>(qw);
    contract_kv_kernel<<<S_LEN, blk>>>(kw);

    /* attention */
    attn_kernel<<<dim3(S_LEN / 64, NH), blk, ATTN_SMEM_BYTES>>>(idx);

    /* output projection (tensor cores) */
    split_kernel<<<2048, blk>>>(pAtt, patth, pattl, S_LEN * HIDDEN);
    hgemm_kernel<<<dim3(16, MB), blk>>>(patth, pattl, pWoh, pWol, out,
                                        HIDDEN, HIDDEN);
}

// round 9
// speedup vs baseline: 7.1353x; 1.5097x over previous
#include <cuda_runtime.h>
#include <cuda_bf16.h>
#include <math.h>
#include <stdint.h>

#define S_LEN   4096
#define HIDDEN  2048
#define NH      8
#define NKVH    4
#define DH      256
#define QR      6
#define KR      2
#define VR      2
#define WINDOW  1024
#define SOFTCAP 50.0f
#define SCALING 0.0625f     /* 256^-0.5 */
#define EPSV    1e-6f

/* ---------------- scratch (device globals; no allocation allowed) -------- */
__device__ float g_Aqkv[S_LEN * 128];
__device__ float g_Bq[S_LEN * QR * DH];
__device__ float g_Bk[S_LEN * KR * DH];
__device__ float g_Bv[S_LEN * VR * DH];
__device__ float g_kA[S_LEN * NKVH * KR];
__device__ float g_kB[S_LEN * KR * DH];
__device__ float g_vA[S_LEN * NKVH * VR];
__device__ float g_vB[S_LEN * VR * DH];

/* bf16 split operands */
__device__ __nv_bfloat16 g_xh [S_LEN * HIDDEN];
__device__ __nv_bfloat16 g_xl [S_LEN * HIDDEN];
__device__ __nv_bfloat16 g_WBq_h[1536 * HIDDEN];
__device__ __nv_bfloat16 g_WBq_l[1536 * HIDDEN];
__device__ __nv_bfloat16 g_WBk_h[ 512 * HIDDEN];
__device__ __nv_bfloat16 g_WBk_l[ 512 * HIDDEN];
__device__ __nv_bfloat16 g_WBv_h[ 512 * HIDDEN];
__device__ __nv_bfloat16 g_WBv_l[ 512 * HIDDEN];
__device__ __nv_bfloat16 g_Wo_h[HIDDEN * HIDDEN];
__device__ __nv_bfloat16 g_Wo_l[HIDDEN * HIDDEN];
__device__ __nv_bfloat16 g_WA_h[128 * HIDDEN];
__device__ __nv_bfloat16 g_WA_l[128 * HIDDEN];

/* bf16 split q/k/v and attention output */
__device__ __nv_bfloat16 g_qh[S_LEN * NH * DH];
__device__ __nv_bfloat16 g_ql[S_LEN * NH * DH];
__device__ __nv_bfloat16 g_kh[S_LEN * NKVH * DH];
__device__ __nv_bfloat16 g_kl[S_LEN * NKVH * DH];
__device__ __nv_bfloat16 g_vh[S_LEN * NKVH * DH];
__device__ __nv_bfloat16 g_vl[S_LEN * NKVH * DH];
__device__ __nv_bfloat16 g_atth[S_LEN * HIDDEN];
__device__ __nv_bfloat16 g_attl[S_LEN * HIDDEN];

/* ---------------- fp32 -> (bf16 hi, bf16 lo) split ----------------------- */
__global__ void split_kernel(const float* __restrict__ in,
                             __nv_bfloat16* __restrict__ hi,
                             __nv_bfloat16* __restrict__ lo, int n)
{
    for (int i = blockIdx.x * 256 + threadIdx.x; i < n; i += gridDim.x * 256) {
        const float a = in[i];
        const __nv_bfloat16 h = __float2bfloat16(a);
        hi[i] = h;
        lo[i] = __float2bfloat16(a - __bfloat162float(h));
    }
}

/* ----- concat W_A_q(48) | W_A_k(8) | W_A_v(8) | zeros -> [128][2048] ----- */
__global__ void wacat_kernel(const float* __restrict__ WAq,
                             const float* __restrict__ WAk,
                             const float* __restrict__ WAv)
{
    for (int i = blockIdx.x * 256 + threadIdx.x; i < 128 * HIDDEN;
         i += gridDim.x * 256) {
        const int row = i >> 11, col = i & 2047;
        float v = 0.f;
        if (row < 48)       v = WAq[row * HIDDEN + col];
        else if (row < 56)  v = WAk[(row - 48) * HIDDEN + col];
        else if (row < 64)  v = WAv[(row - 56) * HIDDEN + col];
        const __nv_bfloat16 h = __float2bfloat16(v);
        g_WA_h[i] = h;
        g_WA_l[i] = __float2bfloat16(v - __bfloat162float(h));
    }
}

/* ---------------- MMA / ldmatrix macros ---------------------------------- */
#define LDSM4(d, a) \
    asm volatile("ldmatrix.sync.aligned.m8n8.x4.shared.b16 {%0,%1,%2,%3}, [%4];" \
        : "=r"(d[0]), "=r"(d[1]), "=r"(d[2]), "=r"(d[3]) : "r"(a))

#define LDSM4T(d, a) \
    asm volatile("ldmatrix.sync.aligned.m8n8.x4.trans.shared.b16 {%0,%1,%2,%3}, [%4];" \
        : "=r"(d[0]), "=r"(d[1]), "=r"(d[2]), "=r"(d[3]) : "r"(a))

#define MMA16816(c, a, b0, b1) \
    asm volatile("mma.sync.aligned.m16n8k16.row.col.f32.bf16.bf16.f32 " \
        "{%0,%1,%2,%3}, {%4,%5,%6,%7}, {%8,%9}, {%0,%1,%2,%3};" \
        : "+f"(c[0]), "+f"(c[1]), "+f"(c[2]), "+f"(c[3]) \
        : "r"(a[0]), "r"(a[1]), "r"(a[2]), "r"(a[3]), "r"(b0), "r"(b1))

/* ---------------- HMMA split-bf16 GEMM: C[M,N] = A @ W^T ------------------ */
__global__ __launch_bounds__(256) void hgemm_kernel(
    const __nv_bfloat16* __restrict__ Ah, const __nv_bfloat16* __restrict__ Al,
    const __nv_bfloat16* __restrict__ Wh, const __nv_bfloat16* __restrict__ Wl,
    float* __restrict__ C, int N, int K)
{
    __shared__ __align__(16) __nv_bfloat16 sm[2][4][128 * 24];
    const int tid  = threadIdx.x;
    const int m0   = blockIdx.y * 128, n0 = blockIdx.x * 128;
    const int warp = tid >> 5, lane = tid & 31;
    const int wm   = (warp & 1) * 64, wn = (warp >> 1) * 32;

    const int ldr = tid >> 1, lds8 = (tid & 1) * 8;
    const __nv_bfloat16* gAh = Ah + (size_t)(m0 + ldr) * K + lds8;
    const __nv_bfloat16* gAl = Al + (size_t)(m0 + ldr) * K + lds8;
    const __nv_bfloat16* gWh = Wh + (size_t)(n0 + ldr) * K + lds8;
    const __nv_bfloat16* gWl = Wl + (size_t)(n0 + ldr) * K + lds8;
    const int stoff = ldr * 24 + lds8;

    const int r8   = lane & 7, tq = lane >> 3;
    const int lrow = (tq & 1) * 8 + r8;
    const int lcol = (tq >> 1) * 8;
    const uint32_t smBase = (uint32_t)__cvta_generic_to_shared(&sm[0][0][0]);
    const uint32_t aoff = ((wm + lrow) * 24 + lcol) * 2;
    const uint32_t boff = ((wn + lrow) * 24 + lcol) * 2;

    float c[4][4][4];
    #pragma unroll
    for (int mt = 0; mt < 4; mt++)
        #pragma unroll
        for (int nt = 0; nt < 4; nt++)
            #pragma unroll
            for (int f = 0; f < 4; f++) c[mt][nt][f] = 0.f;

    {
        uint4 va = *(const uint4*)gAh;
        uint4 vb = *(const uint4*)gAl;
        uint4 vc = *(const uint4*)gWh;
        uint4 vd = *(const uint4*)gWl;
        *(uint4*)&sm[0][0][stoff] = va;
        *(uint4*)&sm[0][1][stoff] = vb;
        *(uint4*)&sm[0][2][stoff] = vc;
        *(uint4*)&sm[0][3][stoff] = vd;
    }

    const int NS = K >> 4;
    for (int ks = 0; ks < NS; ks++) {
        __syncthreads();
        const int buf = ks & 1;
        if (ks + 1 < NS) {
            const int ko = (ks + 1) << 4;
            uint4 va = *(const uint4*)(gAh + ko);
            uint4 vb = *(const uint4*)(gAl + ko);
            uint4 vc = *(const uint4*)(gWh + ko);
            uint4 vd = *(const uint4*)(gWl + ko);
            const int nb = buf ^ 1;
            *(uint4*)&sm[nb][0][stoff] = va;
            *(uint4*)&sm[nb][1][stoff] = vb;
            *(uint4*)&sm[nb][2][stoff] = vc;
            *(uint4*)&sm[nb][3][stoff] = vd;
        }
        const uint32_t base = smBase + (uint32_t)buf * (4 * 3072 * 2);
        uint32_t ah[4][4], al[4][4], bh[2][4], bl[2][4];
        #pragma unroll
        for (int mt = 0; mt < 4; mt++) {
            LDSM4(ah[mt], base + 0 * 6144 + aoff + mt * 768);
            LDSM4(al[mt], base + 1 * 6144 + aoff + mt * 768);
        }
        #pragma unroll
        for (int p = 0; p < 2; p++) {
            LDSM4(bh[p], base + 2 * 6144 + boff + p * 768);
            LDSM4(bl[p], base + 3 * 6144 + boff + p * 768);
        }
        #pragma unroll
        for (int mt = 0; mt < 4; mt++)
            #pragma unroll
            for (int nt = 0; nt < 4; nt++) {
                const int p = nt >> 1, q = nt & 1;
                MMA16816(c[mt][nt], ah[mt], bh[p][q], bh[p][q + 2]);
                MMA16816(c[mt][nt], ah[mt], bl[p][q], bl[p][q + 2]);
                MMA16816(c[mt][nt], al[mt], bh[p][q], bh[p][q + 2]);
            }
    }

    const int gid = lane >> 2, tg = lane & 3;
    #pragma unroll
    for (int mt = 0; mt < 4; mt++)
        #pragma unroll
        for (int nt = 0; nt < 4; nt++) {
            const int row = m0 + wm + mt * 16 + gid;
            const int col = n0 + wn + nt * 8 + tg * 2;
            float2 v0 = make_float2(c[mt][nt][0], c[mt][nt][1]);
            float2 v1 = make_float2(c[mt][nt][2], c[mt][nt][3]);
            *(float2*)&C[(size_t)row * N + col]       = v0;
            *(float2*)&C[(size_t)(row + 8) * N + col] = v1;
        }
}

/* ---------------- RoPE on B_q in place: [S, QR, D] ----------------------- */
__global__ void rope_q_kernel(const float* __restrict__ fc,
                              const float* __restrict__ fs)
{
    const int s = blockIdx.x;
    const int i = threadIdx.x;
    const float c = fc[s * 128 + i], sn = fs[s * 128 + i];
    #pragma unroll
    for (int r = 0; r < QR; r++) {
        float* p = &g_Bq[(s * QR + r) * DH + 2 * i];
        const float x1 = p[0], x2 = p[1];
        p[0] = x1 * c - x2 * sn;
        p[1] = x1 * sn + x2 * c;
    }
}

/* ---------------- copy cache inputs into scratch caches ------------------ */
__global__ void copy_caches_kernel(const float* __restrict__ kcA,
                                   const float* __restrict__ kcB,
                                   const float* __restrict__ vcA,
                                   const float* __restrict__ vcB)
{
    const int i = blockIdx.x * 256 + threadIdx.x;
    if (i < S_LEN * 8)   { g_kA[i] = kcA[i]; g_vA[i] = vcA[i]; }
    if (i < S_LEN * 512) { g_kB[i] = kcB[i]; g_vB[i] = vcB[i]; }
}

/* -------- scatter A_k / A_v / RoPE(B_k) / B_v into caches at idx[s] ------ */
__global__ void scatter_kernel(const int* __restrict__ idx,
                               const float* __restrict__ fc,
                               const float* __restrict__ fs)
{
    const int s = blockIdx.x;
    const int tid = threadIdx.x;
    const int t = idx[s];
    if (tid < 8) {
        g_kA[t * 8 + tid] = g_Aqkv[s * 128 + 48 + tid];
        g_vA[t * 8 + tid] = g_Aqkv[s * 128 + 56 + tid];
    }
    const int r = tid >> 7, i = tid & 127;
    const float c = fc[s * 128 + i], sn = fs[s * 128 + i];
    const float* p = &g_Bk[(s * KR + r) * DH + 2 * i];
    const float x1 = p[0], x2 = p[1];
    g_kB[(t * KR + r) * DH + 2 * i]     = x1 * c - x2 * sn;
    g_kB[(t * KR + r) * DH + 2 * i + 1] = x1 * sn + x2 * c;
    g_vB[t * 512 + tid]       = g_Bv[s * 512 + tid];
    g_vB[t * 512 + 256 + tid] = g_Bv[s * 512 + 256 + tid];
}

/* -------- q = RMSNorm(sum_r Aq*Bq/QR)*(1+qw)*SCALING -> bf16 hi/lo ------- */
__global__ void contract_q_kernel(const float* __restrict__ qw)
{
    const int s = blockIdx.x;
    const int d = threadIdx.x;
    __shared__ float a[48];
    __shared__ float wsum[8][8];
    if (d < 48) a[d] = g_Aqkv[s * 128 + d];
    __syncthreads();

    float bq[QR];
    #pragma unroll
    for (int r = 0; r < QR; r++) bq[r] = g_Bq[s * (QR * DH) + r * DH + d];

    float acc[NH];
    #pragma unroll
    for (int h = 0; h < NH; h++) {
        float v = 0.f;
        #pragma unroll
        for (int r = 0; r < QR; r++) v += a[h * QR + r] * bq[r];
        acc[h] = v * (1.0f / (float)QR);
    }
    const int lane = d & 31, warp = d >> 5;
    #pragma unroll
    for (int h = 0; h < NH; h++) {
        float v = acc[h] * acc[h];
        for (int o = 16; o > 0; o >>= 1) v += __shfl_xor_sync(0xffffffffu, v, o);
        if (lane == 0) wsum[h][warp] = v;
    }
    __syncthreads();
    const float w = 1.0f + qw[d];
    #pragma unroll
    for (int h = 0; h < NH; h++) {
        float tot = 0.f;
        #pragma unroll
        for (int i = 0; i < 8; i++) tot += wsum[h][i];
        const float rn = rsqrtf(tot * (1.0f / (float)DH) + EPSV);
        const float val = acc[h] * rn * w * SCALING;
        const __nv_bfloat16 hi = __float2bfloat16(val);
        g_qh[(s * NH + h) * DH + d] = hi;
        g_ql[(s * NH + h) * DH + d] =
            __float2bfloat16(val - __bfloat162float(hi));
    }
}

/* -------- k = RMSNorm(kA*kB/KR)*(1+kw); v = vA*vB/VR -> bf16 hi/lo ------- */
__global__ void contract_kv_kernel(const float* __restrict__ kw)
{
    const int t = blockIdx.x;
    const int d = threadIdx.x;
    __shared__ float a[16];
    __shared__ float wsum[4][8];
    if (d < 8)               a[d] = g_kA[t * 8 + d];
    else if (d < 16)         a[d] = g_vA[t * 8 + (d - 8)];
    __syncthreads();

    const float kb0 = g_kB[t * 512 + d],       kb1 = g_kB[t * 512 + 256 + d];
    const float vb0 = g_vB[t * 512 + d],       vb1 = g_vB[t * 512 + 256 + d];

    float kacc[NKVH], vacc[NKVH];
    #pragma unroll
    for (int kh = 0; kh < NKVH; kh++) {
        kacc[kh] = 0.5f * (a[kh * 2] * kb0 + a[kh * 2 + 1] * kb1);
        vacc[kh] = 0.5f * (a[8 + kh * 2] * vb0 + a[8 + kh * 2 + 1] * vb1);
    }
    const int lane = d & 31, warp = d >> 5;
    #pragma unroll
    for (int kh = 0; kh < NKVH; kh++) {
        float v = kacc[kh] * kacc[kh];
        for (int o = 16; o > 0; o >>= 1) v += __shfl_xor_sync(0xffffffffu, v, o);
        if (lane == 0) wsum[kh][warp] = v;
    }
    __syncthreads();
    const float w = 1.0f + kw[d];
    #pragma unroll
    for (int kh = 0; kh < NKVH; kh++) {
        float tot = 0.f;
        #pragma unroll
        for (int i = 0; i < 8; i++) tot += wsum[kh][i];
        const float rn = rsqrtf(tot * (1.0f / (float)DH) + EPSV);
        const float kv = kacc[kh] * rn * w;
        const float vv = vacc[kh];
        const __nv_bfloat16 khi = __float2bfloat16(kv);
        const __nv_bfloat16 vhi = __float2bfloat16(vv);
        const int o = (t * NKVH + kh) * DH + d;
        g_kh[o] = khi;
        g_kl[o] = __float2bfloat16(kv - __bfloat162float(khi));
        g_vh[o] = vhi;
        g_vl[o] = __float2bfloat16(vv - __bfloat162float(vhi));
    }
}

/* ---------------- MMA sliding-window softcapped attention ----------------
 * Block = 64 q x 1 head; 64-key tiles; 8 warps (4 m-groups x 2 n-groups).
 * QK^T and P*V on tensor cores, 3-term bf16 split each. Scores->probs in
 * registers (C-frag layout == A-frag layout). V via ldmatrix.trans.
 * Fixed softmax shift exp(s-50) (post-tanh |s| <= 50).                     */
#define AT_STRIDE 264
#define AT_TILE_B (64 * AT_STRIDE * 2)
#define AT_QH 0
#define AT_QL (1 * AT_TILE_B)
#define AT_KH (2 * AT_TILE_B)
#define AT_KL (3 * AT_TILE_B)
#define AT_VH (4 * AT_TILE_B)
#define AT_VL (5 * AT_TILE_B)
#define AT_QPOS (6 * AT_TILE_B)
#define AT_RSUM (AT_QPOS + 256)
#define ATTN_SMEM_BYTES (AT_RSUM + 256)

__device__ __forceinline__ uint32_t pack_bf16x2(__nv_bfloat16 lo, __nv_bfloat16 hi)
{
    return ((uint32_t)__bfloat16_as_ushort(hi) << 16) |
           (uint32_t)__bfloat16_as_ushort(lo);
}

__global__ __launch_bounds__(256) void attn_kernel(const int* __restrict__ idx)
{
    extern __shared__ char sm[];
    const int s0  = blockIdx.x * 64;
    const int h   = blockIdx.y;
    const int kvh = h >> 1;
    const int tid = threadIdx.x, warp = tid >> 5, lane = tid & 31;
    const int mgrp = warp & 3, ngrp = warp >> 2;
    const int m0 = mgrp * 16, n0 = ngrp * 32;
    const int r8 = lane & 7, tq = lane >> 3;
    const int lrA = (tq & 1) * 8 + r8, lcA = (tq >> 1) * 8;   /* non-trans */
    const int lrT = (tq >> 1) * 8 + r8, lcT = (tq & 1) * 8;   /* trans     */
    const int gid = lane >> 2, qd = lane & 3;

    const uint32_t smB = (uint32_t)__cvta_generic_to_shared(sm);
    int*   qpos  = (int*)(sm + AT_QPOS);
    float* rsumS = (float*)(sm + AT_RSUM);

    /* load q hi/lo into smem (once) */
    #pragma unroll
    for (int c = 0; c < 8; c++) {
        const int i4 = tid + c * 256;
        const int row = i4 >> 5, col = (i4 & 31) * 8;
        const size_t g = ((size_t)(s0 + row) * NH + h) * DH + col;
        const int so = (row * AT_STRIDE + col) * 2;
        *(uint4*)(sm + AT_QH + so) = *(const uint4*)(g_qh + g);
        *(uint4*)(sm + AT_QL + so) = *(const uint4*)(g_ql + g);
    }
    if (tid < 64) qpos[tid] = idx[s0 + tid];

    float o[32][4];
    #pragma unroll
    for (int nt = 0; nt < 32; nt++)
        #pragma unroll
        for (int f = 0; f < 4; f++) o[nt][f] = 0.f;
    float rs0 = 0.f, rs1 = 0.f;

    const uint32_t aQH  = smB + AT_QH + ((m0 + lrA) * AT_STRIDE + lcA) * 2;
    const uint32_t aQL  = smB + AT_QL + ((m0 + lrA) * AT_STRIDE + lcA) * 2;
    const uint32_t bK0H = smB + AT_KH + ((n0 + lrA) * AT_STRIDE + lcA) * 2;
    const uint32_t bK0L = smB + AT_KL + ((n0 + lrA) * AT_STRIDE + lcA) * 2;
    const uint32_t bK1H = bK0H + 16 * AT_STRIDE * 2;
    const uint32_t bK1L = bK0L + 16 * AT_STRIDE * 2;

    int tlo = s0 - (WINDOW - 1);
    if (tlo < 0) tlo = 0;
    tlo &= ~63;

    for (int t0 = tlo; t0 < s0 + 64; t0 += 64) {
        /* load k, v hi/lo tiles */
        #pragma unroll
        for (int c = 0; c < 8; c++) {
            const int i4 = tid + c * 256;
            const int row = i4 >> 5, col = (i4 & 31) * 8;
            const size_t g = ((size_t)(t0 + row) * NKVH + kvh) * DH + col;
            const int so = (row * AT_STRIDE + col) * 2;
            *(uint4*)(sm + AT_KH + so) = *(const uint4*)(g_kh + g);
            *(uint4*)(sm + AT_KL + so) = *(const uint4*)(g_kl + g);
            *(uint4*)(sm + AT_VH + so) = *(const uint4*)(g_vh + g);
            *(uint4*)(sm + AT_VL + so) = *(const uint4*)(g_vl + g);
        }
        __syncthreads();

        /* ---- QK^T: warp tile 16x32 ---- */
        float sc[4][4];
        #pragma unroll
        for (int nt = 0; nt < 4; nt++)
            #pragma unroll
            for (int f = 0; f < 4; f++) sc[nt][f] = 0.f;

        #pragma unroll
        for (int ks = 0; ks < 16; ks++) {
            const uint32_t ko = ks * 32;
            uint32_t aH[4], aL[4], b0H[4], b0L[4], b1H[4], b1L[4];
            LDSM4(aH, aQH + ko);
            LDSM4(aL, aQL + ko);
            LDSM4(b0H, bK0H + ko);
            LDSM4(b0L, bK0L + ko);
            LDSM4(b1H, bK1H + ko);
            LDSM4(b1L, bK1L + ko);
            MMA16816(sc[0], aH, b0H[0], b0H[2]);
            MMA16816(sc[0], aH, b0L[0], b0L[2]);
            MMA16816(sc[0], aL, b0H[0], b0H[2]);
            MMA16816(sc[1], aH, b0H[1], b0H[3]);
            MMA16816(sc[1], aH, b0L[1], b0L[3]);
            MMA16816(sc[1], aL, b0H[1], b0H[3]);
            MMA16816(sc[2], aH, b1H[0], b1H[2]);
            MMA16816(sc[2], aH, b1L[0], b1L[2]);
            MMA16816(sc[2], aL, b1H[0], b1H[2]);
            MMA16816(sc[3], aH, b1H[1], b1H[3]);
            MMA16816(sc[3], aH, b1L[1], b1L[3]);
            MMA16816(sc[3], aL, b1H[1], b1H[3]);
        }

        /* ---- softcap + mask + exp(s-50); pack P as A-fragments ---- */
        const int qp0 = qpos[m0 + gid], qp1 = qpos[m0 + gid + 8];
        uint32_t aPh[2][4], aPl[2][4];
        #pragma unroll
        for (int nt = 0; nt < 4; nt++) {
            const int colb = n0 + 8 * nt + 2 * qd;
            const int kp0 = t0 + colb, kp1 = kp0 + 1;
            float p[4];
            {
                const float e = tanhf(sc[nt][0] * (1.0f/SOFTCAP)) * SOFTCAP;
                const int d = qp0 - kp0;
                p[0] = (d >= 0 && d < WINDOW) ? __expf(e - SOFTCAP) : 0.f;
            }
            {
                const float e = tanhf(sc[nt][1] * (1.0f/SOFTCAP)) * SOFTCAP;
                const int d = qp0 - kp1;
                p[1] = (d >= 0 && d < WINDOW) ? __expf(e - SOFTCAP) : 0.f;
            }
            {
                const float e = tanhf(sc[nt][2] * (1.0f/SOFTCAP)) * SOFTCAP;
                const int d = qp1 - kp0;
                p[2] = (d >= 0 && d < WINDOW) ? __expf(e - SOFTCAP) : 0.f;
            }
            {
                const float e = tanhf(sc[nt][3] * (1.0f/SOFTCAP)) * SOFTCAP;
                const int d = qp1 - kp1;
                p[3] = (d >= 0 && d < WINDOW) ? __expf(e - SOFTCAP) : 0.f;
            }
            rs0 += p[0] + p[1];
            rs1 += p[2] + p[3];
            const __nv_bfloat16 h0 = __float2bfloat16(p[0]);
            const __nv_bfloat16 h1 = __float2bfloat16(p[1]);
            const __nv_bfloat16 h2 = __float2bfloat16(p[2]);
            const __nv_bfloat16 h3 = __float2bfloat16(p[3]);
            const __nv_bfloat16 l0 = __float2bfloat16(p[0] - __bfloat162float(h0));
            const __nv_bfloat16 l1 = __float2bfloat16(p[1] - __bfloat162float(h1));
            const __nv_bfloat16 l2 = __float2bfloat16(p[2] - __bfloat162float(h2));
            const __nv_bfloat16 l3 = __float2bfloat16(p[3] - __bfloat162float(h3));
            const int j = nt >> 1, r = (nt & 1) * 2;
            aPh[j][r + 0] = pack_bf16x2(h0, h1);
            aPh[j][r + 1] = pack_bf16x2(h2, h3);
            aPl[j][r + 0] = pack_bf16x2(l0, l1);
            aPl[j][r + 1] = pack_bf16x2(l2, l3);
        }

        /* ---- P*V: warp's 32 keys, all 256 dims, via trans ldmatrix ---- */
        #pragma unroll
        for (int j = 0; j < 2; j++) {
            const int kb = n0 + 16 * j;
            const uint32_t vBH = smB + AT_VH + ((kb + lrT) * AT_STRIDE + lcT) * 2;
            const uint32_t vBL = smB + AT_VL + ((kb + lrT) * AT_STRIDE + lcT) * 2;
            #pragma unroll
            for (int ng = 0; ng < 16; ng++) {
                uint32_t vh4[4], vl4[4];
                LDSM4T(vh4, vBH + ng * 32);
                LDSM4T(vl4, vBL + ng * 32);
                MMA16816(o[2*ng+0], aPh[j], vh4[0], vh4[2]);
                MMA16816(o[2*ng+0], aPh[j], vl4[0], vl4[2]);
                MMA16816(o[2*ng+0], aPl[j], vh4[0], vh4[2]);
                MMA16816(o[2*ng+1], aPh[j], vh4[1], vh4[3]);
                MMA16816(o[2*ng+1], aPh[j], vl4[1], vl4[3]);
                MMA16816(o[2*ng+1], aPl[j], vh4[1], vh4[3]);
            }
        }
        __syncthreads();
    }

    /* quad-reduce row sums (all 4 lanes of quad end with the total) */
    rs0 += __shfl_xor_sync(0xffffffffu, rs0, 1);
    rs0 += __shfl_xor_sync(0xffffffffu, rs0, 2);
    rs1 += __shfl_xor_sync(0xffffffffu, rs1, 1);
    rs1 += __shfl_xor_sync(0xffffffffu, rs1, 2);

    float* scratch = (float*)(sm + AT_KH);   /* reuse k region: 64x256 f32 */
    if (ngrp == 1) {
        if (qd == 0) {
            rsumS[m0 + gid]     = rs0;
            rsumS[m0 + gid + 8] = rs1;
        }
        #pragma unroll
        for (int nt = 0; nt < 32; nt++) {
            const int colb = 8 * nt + 2 * qd;
            scratch[(m0 + gid)     * 256 + colb]     = o[nt][0];
            scratch[(m0 + gid)     * 256 + colb + 1] = o[nt][1];
            scratch[(m0 + gid + 8) * 256 + colb]     = o[nt][2];
            scratch[(m0 + gid + 8) * 256 + colb + 1] = o[nt][3];
        }
    }
    __syncthreads();
    if (ngrp == 0) {
        const float inv0 = 1.0f / (rs0 + rsumS[m0 + gid]);
        const float inv1 = 1.0f / (rs1 + rsumS[m0 + gid + 8]);
        const int row0 = s0 + m0 + gid, row1 = row0 + 8;
        #pragma unroll
        for (int nt = 0; nt < 32; nt++) {
            const int colb = 8 * nt + 2 * qd;
            const float v0 = (o[nt][0] + scratch[(m0+gid)  *256 + colb    ]) * inv0;
            const float v1 = (o[nt][1] + scratch[(m0+gid)  *256 + colb + 1]) * inv0;
            const float v2 = (o[nt][2] + scratch[(m0+gid+8)*256 + colb    ]) * inv1;
            const float v3 = (o[nt][3] + scratch[(m0+gid+8)*256 + colb + 1]) * inv1;
            const __nv_bfloat16 h0 = __float2bfloat16(v0);
            const __nv_bfloat16 h1 = __float2bfloat16(v1);
            const __nv_bfloat16 h2 = __float2bfloat16(v2);
            const __nv_bfloat16 h3 = __float2bfloat16(v3);
            const uint32_t hi01 = pack_bf16x2(h0, h1);
            const uint32_t hi23 = pack_bf16x2(h2, h3);
            const uint32_t lo01 = pack_bf16x2(
                __float2bfloat16(v0 - __bfloat162float(h0)),
                __float2bfloat16(v1 - __bfloat162float(h1)));
            const uint32_t lo23 = pack_bf16x2(
                __float2bfloat16(v2 - __bfloat162float(h2)),
                __float2bfloat16(v3 - __bfloat162float(h3)));
            *(uint32_t*)&g_atth[(size_t)row0 * HIDDEN + h * DH + colb] = hi01;
            *(uint32_t*)&g_attl[(size_t)row0 * HIDDEN + h * DH + colb] = lo01;
            *(uint32_t*)&g_atth[(size_t)row1 * HIDDEN + h * DH + colb] = hi23;
            *(uint32_t*)&g_attl[(size_t)row1 * HIDDEN + h * DH + colb] = lo23;
        }
    }
}

/* ------------------------------- launch ---------------------------------- */
extern "C" void kernel_launch(void* const* d_in, const int* in_sizes, int n_in,
                              void* d_out, int out_size)
{
    const float* x   = (const float*)d_in[0];
    const float* fc  = (const float*)d_in[1];
    const float* fs  = (const float*)d_in[2];
    const float* WAq = (const float*)d_in[3];
    const float* WAk = (const float*)d_in[4];
    const float* WAv = (const float*)d_in[5];
    const float* WBq = (const float*)d_in[6];
    const float* WBk = (const float*)d_in[7];
    const float* WBv = (const float*)d_in[8];
    const float* Wo  = (const float*)d_in[9];
    const float* qw  = (const float*)d_in[10];
    const float* kw  = (const float*)d_in[11];
    const float* kcA = (const float*)d_in[12];
    const float* kcB = (const float*)d_in[13];
    const float* vcA = (const float*)d_in[14];
    const float* vcB = (const float*)d_in[15];
    const int*   idx = (const int*)d_in[16];
    float* out = (float*)d_out;

    float *pAqkv, *pBq, *pBk, *pBv;
    __nv_bfloat16 *pxh, *pxl, *pWBqh, *pWBql, *pWBkh, *pWBkl, *pWBvh, *pWBvl;
    __nv_bfloat16 *pWoh, *pWol, *pWAh, *pWAl, *patth, *pattl;
    cudaGetSymbolAddress((void**)&pAqkv, g_Aqkv);
    cudaGetSymbolAddress((void**)&pBq,   g_Bq);
    cudaGetSymbolAddress((void**)&pBk,   g_Bk);
    cudaGetSymbolAddress((void**)&pBv,   g_Bv);
    cudaGetSymbolAddress((void**)&pxh,   g_xh);
    cudaGetSymbolAddress((void**)&pxl,   g_xl);
    cudaGetSymbolAddress((void**)&pWBqh, g_WBq_h);
    cudaGetSymbolAddress((void**)&pWBql, g_WBq_l);
    cudaGetSymbolAddress((void**)&pWBkh, g_WBk_h);
    cudaGetSymbolAddress((void**)&pWBkl, g_WBk_l);
    cudaGetSymbolAddress((void**)&pWBvh, g_WBv_h);
    cudaGetSymbolAddress((void**)&pWBvl, g_WBv_l);
    cudaGetSymbolAddress((void**)&pWoh,  g_Wo_h);
    cudaGetSymbolAddress((void**)&pWol,  g_Wo_l);
    cudaGetSymbolAddress((void**)&pWAh,  g_WA_h);
    cudaGetSymbolAddress((void**)&pWAl,  g_WA_l);
    cudaGetSymbolAddress((void**)&patth, g_atth);
    cudaGetSymbolAddress((void**)&pattl, g_attl);

    cudaFuncSetAttribute(attn_kernel,
                         cudaFuncAttributeMaxDynamicSharedMemorySize,
                         ATTN_SMEM_BYTES);

    const dim3 blk(256);
    const int MB = S_LEN / 128;   /* 32 */

    /* split conversions */
    split_kernel<<<2048, blk>>>(x,   pxh,   pxl,   S_LEN * HIDDEN);
    split_kernel<<<2048, blk>>>(WBq, pWBqh, pWBql, 1536 * HIDDEN);
    split_kernel<<<1024, blk>>>(WBk, pWBkh, pWBkl,  512 * HIDDEN);
    split_kernel<<<1024, blk>>>(WBv, pWBvh, pWBvl,  512 * HIDDEN);
    split_kernel<<<2048, blk>>>(Wo,  pWoh,  pWol,  HIDDEN * HIDDEN);
    wacat_kernel<<<512, blk>>>(WAq, WAk, WAv);

    /* projections (tensor cores) */
    hgemm_kernel<<<dim3( 1, MB), blk>>>(pxh, pxl, pWAh,  pWAl,  pAqkv, 128, HIDDEN);
    hgemm_kernel<<<dim3(12, MB), blk>>>(pxh, pxl, pWBqh, pWBql, pBq, 1536, HIDDEN);
    hgemm_kernel<<<dim3( 4, MB), blk>>>(pxh, pxl, pWBkh, pWBkl, pBk,  512, HIDDEN);
    hgemm_kernel<<<dim3( 4, MB), blk>>>(pxh, pxl, pWBvh, pWBvl, pBv,  512, HIDDEN);

    /* rope on B_q */
    rope_q_kernel<<<S_LEN, 128>>>(fc, fs);

    /* caches */
    copy_caches_kernel<<<(S_LEN * 512 + 255) / 256, blk>>>(kcA, kcB, vcA, vcB);
    scatter_kernel<<<S_LEN, blk>>>(idx, fc, fs);

    /* tensor-product contraction + rmsnorm -> bf16 hi/lo */
    contract_q_kernel <<<S_LEN, blk>>>(qw);
    contract_kv_kernel<<<S_LEN, blk>>>(kw);

    /* attention (tensor cores) */
    attn_kernel<<<dim3(S_LEN / 64, NH), blk, ATTN_SMEM_BYTES>>>(idx);

    /* output projection (tensor cores) */
    hgemm_kernel<<<dim3(16, MB), blk>>>(patth, pattl, pWoh, pWol, out,
                                        HIDDEN, HIDDEN);
}

// round 14
// speedup vs baseline: 8.1472x; 1.1418x over previous
#include <cuda_runtime.h>
#include <cuda_bf16.h>
#include <math.h>
#include <stdint.h>

#define S_LEN   4096
#define HIDDEN  2048
#define NH      8
#define NKVH    4
#define DH      256
#define QR      6
#define KR      2
#define VR      2
#define WINDOW  1024
#define SOFTCAP 50.0f
#define SCALING 0.0625f     /* 256^-0.5 */
#define EPSV    1e-6f

/* merged projection layout: [Aqkv(128) | Bq(1536) | Bk(512) | Bv(512)] */
#define NPROJ   2688
#define OFF_A   0
#define OFF_BQ  128
#define OFF_BK  1664
#define OFF_BV  2176

/* ---------------- scratch (device globals; no allocation allowed) -------- */
__device__ float g_proj[S_LEN * NPROJ];
__device__ float g_kA[S_LEN * NKVH * KR];
__device__ float g_kB[S_LEN * KR * DH];
__device__ float g_vA[S_LEN * NKVH * VR];
__device__ float g_vB[S_LEN * VR * DH];

/* bf16 split operands */
__device__ __nv_bfloat16 g_xh [S_LEN * HIDDEN];
__device__ __nv_bfloat16 g_xl [S_LEN * HIDDEN];
__device__ __nv_bfloat16 g_Wcat_h[NPROJ * HIDDEN];
__device__ __nv_bfloat16 g_Wcat_l[NPROJ * HIDDEN];
__device__ __nv_bfloat16 g_Wo_h[HIDDEN * HIDDEN];
__device__ __nv_bfloat16 g_Wo_l[HIDDEN * HIDDEN];

/* bf16 split q/k/v and attention output */
__device__ __nv_bfloat16 g_qh[S_LEN * NH * DH];
__device__ __nv_bfloat16 g_ql[S_LEN * NH * DH];
__device__ __nv_bfloat16 g_kh[S_LEN * NKVH * DH];
__device__ __nv_bfloat16 g_kl[S_LEN * NKVH * DH];
__device__ __nv_bfloat16 g_vh[S_LEN * NKVH * DH];
__device__ __nv_bfloat16 g_vl[S_LEN * NKVH * DH];
__device__ __nv_bfloat16 g_atth[S_LEN * HIDDEN];
__device__ __nv_bfloat16 g_attl[S_LEN * HIDDEN];

/* ---------------- fp32 -> (bf16 hi, bf16 lo) split ----------------------- */
__global__ void split_kernel(const float* __restrict__ in,
                             __nv_bfloat16* __restrict__ hi,
                             __nv_bfloat16* __restrict__ lo, int n)
{
    for (int i = blockIdx.x * 256 + threadIdx.x; i < n; i += gridDim.x * 256) {
        const float a = in[i];
        const __nv_bfloat16 h = __float2bfloat16(a);
        hi[i] = h;
        lo[i] = __float2bfloat16(a - __bfloat162float(h));
    }
}

/* ----- build concatenated weight [WAq|WAk|WAv|0 ... WBq | WBk | WBv] ----- */
__global__ void prepw_kernel(const float* __restrict__ WAq,
                             const float* __restrict__ WAk,
                             const float* __restrict__ WAv,
                             const float* __restrict__ WBq,
                             const float* __restrict__ WBk,
                             const float* __restrict__ WBv,
                             int row0, int nrows)
{
    const int total = nrows * HIDDEN;
    for (int i = blockIdx.x * 256 + threadIdx.x; i < total;
         i += gridDim.x * 256) {
        const int row = row0 + (i >> 11), col = i & 2047;
        float v = 0.f;
        if (row < 48)            v = WAq[row * HIDDEN + col];
        else if (row < 56)       v = WAk[(row - 48) * HIDDEN + col];
        else if (row < 64)       v = WAv[(row - 56) * HIDDEN + col];
        else if (row < OFF_BQ)   v = 0.f;
        else if (row < OFF_BK)   v = WBq[(row - OFF_BQ) * HIDDEN + col];
        else if (row < OFF_BV)   v = WBk[(row - OFF_BK) * HIDDEN + col];
        else                     v = WBv[(row - OFF_BV) * HIDDEN + col];
        const __nv_bfloat16 h = __float2bfloat16(v);
        g_Wcat_h[row * HIDDEN + col] = h;
        g_Wcat_l[row * HIDDEN + col] =
            __float2bfloat16(v - __bfloat162float(h));
    }
}

/* ---------------- MMA / ldmatrix macros ---------------------------------- */
#define LDSM4(d, a) \
    asm volatile("ldmatrix.sync.aligned.m8n8.x4.shared.b16 {%0,%1,%2,%3}, [%4];" \
        : "=r"(d[0]), "=r"(d[1]), "=r"(d[2]), "=r"(d[3]) : "r"(a))

#define LDSM4T(d, a) \
    asm volatile("ldmatrix.sync.aligned.m8n8.x4.trans.shared.b16 {%0,%1,%2,%3}, [%4];" \
        : "=r"(d[0]), "=r"(d[1]), "=r"(d[2]), "=r"(d[3]) : "r"(a))

#define MMA16816(c, a, b0, b1) \
    asm volatile("mma.sync.aligned.m16n8k16.row.col.f32.bf16.bf16.f32 " \
        "{%0,%1,%2,%3}, {%4,%5,%6,%7}, {%8,%9}, {%0,%1,%2,%3};" \
        : "+f"(c[0]), "+f"(c[1]), "+f"(c[2]), "+f"(c[3]) \
        : "r"(a[0]), "r"(a[1]), "r"(a[2]), "r"(a[3]), "r"(b0), "r"(b1))

/* ---------------- HMMA split-bf16 GEMM: C[M,N] = A @ W^T ------------------ */
__global__ __launch_bounds__(256) void hgemm_kernel(
    const __nv_bfloat16* __restrict__ Ah, const __nv_bfloat16* __restrict__ Al,
    const __nv_bfloat16* __restrict__ Wh, const __nv_bfloat16* __restrict__ Wl,
    float* __restrict__ C, int N, int K)
{
    __shared__ __align__(16) __nv_bfloat16 sm[2][4][128 * 24];
    const int tid  = threadIdx.x;
    const int m0   = blockIdx.y * 128, n0 = blockIdx.x * 128;
    const int warp = tid >> 5, lane = tid & 31;
    const int wm   = (warp & 1) * 64, wn = (warp >> 1) * 32;

    const int ldr = tid >> 1, lds8 = (tid & 1) * 8;
    const __nv_bfloat16* gAh = Ah + (size_t)(m0 + ldr) * K + lds8;
    const __nv_bfloat16* gAl = Al + (size_t)(m0 + ldr) * K + lds8;
    const __nv_bfloat16* gWh = Wh + (size_t)(n0 + ldr) * K + lds8;
    const __nv_bfloat16* gWl = Wl + (size_t)(n0 + ldr) * K + lds8;
    const int stoff = ldr * 24 + lds8;

    const int r8   = lane & 7, tq = lane >> 3;
    const int lrow = (tq & 1) * 8 + r8;
    const int lcol = (tq >> 1) * 8;
    const uint32_t smBase = (uint32_t)__cvta_generic_to_shared(&sm[0][0][0]);
    const uint32_t aoff = ((wm + lrow) * 24 + lcol) * 2;
    const uint32_t boff = ((wn + lrow) * 24 + lcol) * 2;

    float c[4][4][4];
    #pragma unroll
    for (int mt = 0; mt < 4; mt++)
        #pragma unroll
        for (int nt = 0; nt < 4; nt++)
            #pragma unroll
            for (int f = 0; f < 4; f++) c[mt][nt][f] = 0.f;

    {
        uint4 va = *(const uint4*)gAh;
        uint4 vb = *(const uint4*)gAl;
        uint4 vc = *(const uint4*)gWh;
        uint4 vd = *(const uint4*)gWl;
        *(uint4*)&sm[0][0][stoff] = va;
        *(uint4*)&sm[0][1][stoff] = vb;
        *(uint4*)&sm[0][2][stoff] = vc;
        *(uint4*)&sm[0][3][stoff] = vd;
    }

    const int NS = K >> 4;
    for (int ks = 0; ks < NS; ks++) {
        __syncthreads();
        const int buf = ks & 1;
        if (ks + 1 < NS) {
            const int ko = (ks + 1) << 4;
            uint4 va = *(const uint4*)(gAh + ko);
            uint4 vb = *(const uint4*)(gAl + ko);
            uint4 vc = *(const uint4*)(gWh + ko);
            uint4 vd = *(const uint4*)(gWl + ko);
            const int nb = buf ^ 1;
            *(uint4*)&sm[nb][0][stoff] = va;
            *(uint4*)&sm[nb][1][stoff] = vb;
            *(uint4*)&sm[nb][2][stoff] = vc;
            *(uint4*)&sm[nb][3][stoff] = vd;
        }
        const uint32_t base = smBase + (uint32_t)buf * (4 * 3072 * 2);
        uint32_t ah[4][4], al[4][4], bh[2][4], bl[2][4];
        #pragma unroll
        for (int mt = 0; mt < 4; mt++) {
            LDSM4(ah[mt], base + 0 * 6144 + aoff + mt * 768);
            LDSM4(al[mt], base + 1 * 6144 + aoff + mt * 768);
        }
        #pragma unroll
        for (int p = 0; p < 2; p++) {
            LDSM4(bh[p], base + 2 * 6144 + boff + p * 768);
            LDSM4(bl[p], base + 3 * 6144 + boff + p * 768);
        }
        #pragma unroll
        for (int mt = 0; mt < 4; mt++)
            #pragma unroll
            for (int nt = 0; nt < 4; nt++) {
                const int p = nt >> 1, q = nt & 1;
                MMA16816(c[mt][nt], ah[mt], bh[p][q], bh[p][q + 2]);
                MMA16816(c[mt][nt], ah[mt], bl[p][q], bl[p][q + 2]);
                MMA16816(c[mt][nt], al[mt], bh[p][q], bh[p][q + 2]);
            }
    }

    const int gid = lane >> 2, tg = lane & 3;
    #pragma unroll
    for (int mt = 0; mt < 4; mt++)
        #pragma unroll
        for (int nt = 0; nt < 4; nt++) {
            const int row = m0 + wm + mt * 16 + gid;
            const int col = n0 + wn + nt * 8 + tg * 2;
            float2 v0 = make_float2(c[mt][nt][0], c[mt][nt][1]);
            float2 v1 = make_float2(c[mt][nt][2], c[mt][nt][3]);
            *(float2*)&C[(size_t)row * N + col]       = v0;
            *(float2*)&C[(size_t)(row + 8) * N + col] = v1;
        }
}

/* ---------------- RoPE on B_q in place: g_proj Bq region ----------------- */
__global__ void rope_q_kernel(const float* __restrict__ fc,
                              const float* __restrict__ fs)
{
    const int s = blockIdx.x;
    const int i = threadIdx.x;
    const float c = fc[s * 128 + i], sn = fs[s * 128 + i];
    #pragma unroll
    for (int r = 0; r < QR; r++) {
        float* p = &g_proj[(size_t)s * NPROJ + OFF_BQ + r * DH + 2 * i];
        const float x1 = p[0], x2 = p[1];
        p[0] = x1 * c - x2 * sn;
        p[1] = x1 * sn + x2 * c;
    }
}

/* ---------------- copy cache inputs into scratch caches ------------------ */
__global__ void copy_caches_kernel(const float* __restrict__ kcA,
                                   const float* __restrict__ kcB,
                                   const float* __restrict__ vcA,
                                   const float* __restrict__ vcB)
{
    const int i = blockIdx.x * 256 + threadIdx.x;
    if (i < S_LEN * 8)   { g_kA[i] = kcA[i]; g_vA[i] = vcA[i]; }
    if (i < S_LEN * 512) { g_kB[i] = kcB[i]; g_vB[i] = vcB[i]; }
}

/* -------- scatter A_k / A_v / RoPE(B_k) / B_v into caches at idx[s] ------ */
__global__ void scatter_kernel(const int* __restrict__ idx,
                               const float* __restrict__ fc,
                               const float* __restrict__ fs)
{
    const int s = blockIdx.x;
    const int tid = threadIdx.x;
    const int t = idx[s];
    const float* prow = &g_proj[(size_t)s * NPROJ];
    if (tid < 8) {
        g_kA[t * 8 + tid] = prow[48 + tid];
        g_vA[t * 8 + tid] = prow[56 + tid];
    }
    const int r = tid >> 7, i = tid & 127;
    const float c = fc[s * 128 + i], sn = fs[s * 128 + i];
    const float* p = prow + OFF_BK + r * DH + 2 * i;
    const float x1 = p[0], x2 = p[1];
    g_kB[(t * KR + r) * DH + 2 * i]     = x1 * c - x2 * sn;
    g_kB[(t * KR + r) * DH + 2 * i + 1] = x1 * sn + x2 * c;
    g_vB[t * 512 + tid]       = prow[OFF_BV + tid];
    g_vB[t * 512 + 256 + tid] = prow[OFF_BV + 256 + tid];
}

/* -------- q = RMSNorm(sum_r Aq*Bq/QR)*(1+qw)*SCALING -> bf16 hi/lo ------- */
__global__ void contract_q_kernel(const float* __restrict__ qw)
{
    const int s = blockIdx.x;
    const int d = threadIdx.x;
    __shared__ float a[48];
    __shared__ float wsum[8][8];
    const float* prow = &g_proj[(size_t)s * NPROJ];
    if (d < 48) a[d] = prow[d];
    __syncthreads();

    float bq[QR];
    #pragma unroll
    for (int r = 0; r < QR; r++) bq[r] = prow[OFF_BQ + r * DH + d];

    float acc[NH];
    #pragma unroll
    for (int h = 0; h < NH; h++) {
        float v = 0.f;
        #pragma unroll
        for (int r = 0; r < QR; r++) v += a[h * QR + r] * bq[r];
        acc[h] = v * (1.0f / (float)QR);
    }
    const int lane = d & 31, warp = d >> 5;
    #pragma unroll
    for (int h = 0; h < NH; h++) {
        float v = acc[h] * acc[h];
        for (int o = 16; o > 0; o >>= 1) v += __shfl_xor_sync(0xffffffffu, v, o);
        if (lane == 0) wsum[h][warp] = v;
    }
    __syncthreads();
    const float w = 1.0f + qw[d];
    #pragma unroll
    for (int h = 0; h < NH; h++) {
        float tot = 0.f;
        #pragma unroll
        for (int i = 0; i < 8; i++) tot += wsum[h][i];
        const float rn = rsqrtf(tot * (1.0f / (float)DH) + EPSV);
        const float val = acc[h] * rn * w * SCALING;
        const __nv_bfloat16 hi = __float2bfloat16(val);
        g_qh[(s * NH + h) * DH + d] = hi;
        g_ql[(s * NH + h) * DH + d] =
            __float2bfloat16(val - __bfloat162float(hi));
    }
}

/* -------- k = RMSNorm(kA*kB/KR)*(1+kw); v = vA*vB/VR -> bf16 hi/lo ------- */
__global__ void contract_kv_kernel(const float* __restrict__ kw)
{
    const int t = blockIdx.x;
    const int d = threadIdx.x;
    __shared__ float a[16];
    __shared__ float wsum[4][8];
    if (d < 8)               a[d] = g_kA[t * 8 + d];
    else if (d < 16)         a[d] = g_vA[t * 8 + (d - 8)];
    __syncthreads();

    const float kb0 = g_kB[t * 512 + d],       kb1 = g_kB[t * 512 + 256 + d];
    const float vb0 = g_vB[t * 512 + d],       vb1 = g_vB[t * 512 + 256 + d];

    float kacc[NKVH], vacc[NKVH];
    #pragma unroll
    for (int kh = 0; kh < NKVH; kh++) {
        kacc[kh] = 0.5f * (a[kh * 2] * kb0 + a[kh * 2 + 1] * kb1);
        vacc[kh] = 0.5f * (a[8 + kh * 2] * vb0 + a[8 + kh * 2 + 1] * vb1);
    }
    const int lane = d & 31, warp = d >> 5;
    #pragma unroll
    for (int kh = 0; kh < NKVH; kh++) {
        float v = kacc[kh] * kacc[kh];
        for (int o = 16; o > 0; o >>= 1) v += __shfl_xor_sync(0xffffffffu, v, o);
        if (lane == 0) wsum[kh][warp] = v;
    }
    __syncthreads();
    const float w = 1.0f + kw[d];
    #pragma unroll
    for (int kh = 0; kh < NKVH; kh++) {
        float tot = 0.f;
        #pragma unroll
        for (int i = 0; i < 8; i++) tot += wsum[kh][i];
        const float rn = rsqrtf(tot * (1.0f / (float)DH) + EPSV);
        const float kv = kacc[kh] * rn * w;
        const float vv = vacc[kh];
        const __nv_bfloat16 khi = __float2bfloat16(kv);
        const __nv_bfloat16 vhi = __float2bfloat16(vv);
        const int o = (t * NKVH + kh) * DH + d;
        g_kh[o] = khi;
        g_kl[o] = __float2bfloat16(kv - __bfloat162float(khi));
        g_vh[o] = vhi;
        g_vl[o] = __float2bfloat16(vv - __bfloat162float(vhi));
    }
}

/* ---------------- MMA sliding-window softcapped attention ---------------- */
#define AT_STRIDE 264
#define AT_TILE_B (64 * AT_STRIDE * 2)
#define AT_QH 0
#define AT_QL (1 * AT_TILE_B)
#define AT_KH (2 * AT_TILE_B)
#define AT_KL (3 * AT_TILE_B)
#define AT_VH (4 * AT_TILE_B)
#define AT_VL (5 * AT_TILE_B)
#define AT_QPOS (6 * AT_TILE_B)
#define AT_RSUM (AT_QPOS + 256)
#define ATTN_SMEM_BYTES (AT_RSUM + 256)

__device__ __forceinline__ uint32_t pack_bf16x2(__nv_bfloat16 lo, __nv_bfloat16 hi)
{
    return ((uint32_t)__bfloat16_as_ushort(hi) << 16) |
           (uint32_t)__bfloat16_as_ushort(lo);
}

__global__ __launch_bounds__(256) void attn_kernel(const int* __restrict__ idx)
{
    extern __shared__ char sm[];
    const int s0  = blockIdx.x * 64;
    const int h   = blockIdx.y;
    const int kvh = h >> 1;
    const int tid = threadIdx.x, warp = tid >> 5, lane = tid & 31;
    const int mgrp = warp & 3, ngrp = warp >> 2;
    const int m0 = mgrp * 16, n0 = ngrp * 32;
    const int r8 = lane & 7, tq = lane >> 3;
    const int lrA = (tq & 1) * 8 + r8, lcA = (tq >> 1) * 8;
    const int lrT = (tq >> 1) * 8 + r8, lcT = (tq & 1) * 8;
    const int gid = lane >> 2, qd = lane & 3;

    const uint32_t smB = (uint32_t)__cvta_generic_to_shared(sm);
    int*   qpos  = (int*)(sm + AT_QPOS);
    float* rsumS = (float*)(sm + AT_RSUM);

    #pragma unroll
    for (int c = 0; c < 8; c++) {
        const int i4 = tid + c * 256;
        const int row = i4 >> 5, col = (i4 & 31) * 8;
        const size_t g = ((size_t)(s0 + row) * NH + h) * DH + col;
        const int so = (row * AT_STRIDE + col) * 2;
        *(uint4*)(sm + AT_QH + so) = *(const uint4*)(g_qh + g);
        *(uint4*)(sm + AT_QL + so) = *(const uint4*)(g_ql + g);
    }
    if (tid < 64) qpos[tid] = idx[s0 + tid];

    float o[32][4];
    #pragma unroll
    for (int nt = 0; nt < 32; nt++)
        #pragma unroll
        for (int f = 0; f < 4; f++) o[nt][f] = 0.f;
    float rs0 = 0.f, rs1 = 0.f;

    const uint32_t aQH  = smB + AT_QH + ((m0 + lrA) * AT_STRIDE + lcA) * 2;
    const uint32_t aQL  = smB + AT_QL + ((m0 + lrA) * AT_STRIDE + lcA) * 2;
    const uint32_t bK0H = smB + AT_KH + ((n0 + lrA) * AT_STRIDE + lcA) * 2;
    const uint32_t bK0L = smB + AT_KL + ((n0 + lrA) * AT_STRIDE + lcA) * 2;
    const uint32_t bK1H = bK0H + 16 * AT_STRIDE * 2;
    const uint32_t bK1L = bK0L + 16 * AT_STRIDE * 2;

    int tlo = s0 - (WINDOW - 1);
    if (tlo < 0) tlo = 0;
    tlo &= ~63;

    for (int t0 = tlo; t0 < s0 + 64; t0 += 64) {
        #pragma unroll
        for (int c = 0; c < 8; c++) {
            const int i4 = tid + c * 256;
            const int row = i4 >> 5, col = (i4 & 31) * 8;
            const size_t g = ((size_t)(t0 + row) * NKVH + kvh) * DH + col;
            const int so = (row * AT_STRIDE + col) * 2;
            *(uint4*)(sm + AT_KH + so) = *(const uint4*)(g_kh + g);
            *(uint4*)(sm + AT_KL + so) = *(const uint4*)(g_kl + g);
            *(uint4*)(sm + AT_VH + so) = *(const uint4*)(g_vh + g);
            *(uint4*)(sm + AT_VL + so) = *(const uint4*)(g_vl + g);
        }
        __syncthreads();

        float sc[4][4];
        #pragma unroll
        for (int nt = 0; nt < 4; nt++)
            #pragma unroll
            for (int f = 0; f < 4; f++) sc[nt][f] = 0.f;

        #pragma unroll
        for (int ks = 0; ks < 16; ks++) {
            const uint32_t ko = ks * 32;
            uint32_t aH[4], aL[4], b0H[4], b0L[4], b1H[4], b1L[4];
            LDSM4(aH, aQH + ko);
            LDSM4(aL, aQL + ko);
            LDSM4(b0H, bK0H + ko);
            LDSM4(b0L, bK0L + ko);
            LDSM4(b1H, bK1H + ko);
            LDSM4(b1L, bK1L + ko);
            MMA16816(sc[0], aH, b0H[0], b0H[2]);
            MMA16816(sc[0], aH, b0L[0], b0L[2]);
            MMA16816(sc[0], aL, b0H[0], b0H[2]);
            MMA16816(sc[1], aH, b0H[1], b0H[3]);
            MMA16816(sc[1], aH, b0L[1], b0L[3]);
            MMA16816(sc[1], aL, b0H[1], b0H[3]);
            MMA16816(sc[2], aH, b1H[0], b1H[2]);
            MMA16816(sc[2], aH, b1L[0], b1L[2]);
            MMA16816(sc[2], aL, b1H[0], b1H[2]);
            MMA16816(sc[3], aH, b1H[1], b1H[3]);
            MMA16816(sc[3], aH, b1L[1], b1L[3]);
            MMA16816(sc[3], aL, b1H[1], b1H[3]);
        }

        const int qp0 = qpos[m0 + gid], qp1 = qpos[m0 + gid + 8];
        uint32_t aPh[2][4], aPl[2][4];
        #pragma unroll
        for (int nt = 0; nt < 4; nt++) {
            const int colb = n0 + 8 * nt + 2 * qd;
            const int kp0 = t0 + colb, kp1 = kp0 + 1;
            float p[4];
            {
                const float e = tanhf(sc[nt][0] * (1.0f/SOFTCAP)) * SOFTCAP;
                const int d = qp0 - kp0;
                p[0] = (d >= 0 && d < WINDOW) ? __expf(e - SOFTCAP) : 0.f;
            }
            {
                const float e = tanhf(sc[nt][1] * (1.0f/SOFTCAP)) * SOFTCAP;
                const int d = qp0 - kp1;
                p[1] = (d >= 0 && d < WINDOW) ? __expf(e - SOFTCAP) : 0.f;
            }
            {
                const float e = tanhf(sc[nt][2] * (1.0f/SOFTCAP)) * SOFTCAP;
                const int d = qp1 - kp0;
                p[2] = (d >= 0 && d < WINDOW) ? __expf(e - SOFTCAP) : 0.f;
            }
            {
                const float e = tanhf(sc[nt][3] * (1.0f/SOFTCAP)) * SOFTCAP;
                const int d = qp1 - kp1;
                p[3] = (d >= 0 && d < WINDOW) ? __expf(e - SOFTCAP) : 0.f;
            }
            rs0 += p[0] + p[1];
            rs1 += p[2] + p[3];
            const __nv_bfloat16 h0 = __float2bfloat16(p[0]);
            const __nv_bfloat16 h1 = __float2bfloat16(p[1]);
            const __nv_bfloat16 h2 = __float2bfloat16(p[2]);
            const __nv_bfloat16 h3 = __float2bfloat16(p[3]);
            const __nv_bfloat16 l0 = __float2bfloat16(p[0] - __bfloat162float(h0));
            const __nv_bfloat16 l1 = __float2bfloat16(p[1] - __bfloat162float(h1));
            const __nv_bfloat16 l2 = __float2bfloat16(p[2] - __bfloat162float(h2));
            const __nv_bfloat16 l3 = __float2bfloat16(p[3] - __bfloat162float(h3));
            const int j = nt >> 1, r = (nt & 1) * 2;
            aPh[j][r + 0] = pack_bf16x2(h0, h1);
            aPh[j][r + 1] = pack_bf16x2(h2, h3);
            aPl[j][r + 0] = pack_bf16x2(l0, l1);
            aPl[j][r + 1] = pack_bf16x2(l2, l3);
        }

        #pragma unroll
        for (int j = 0; j < 2; j++) {
            const int kb = n0 + 16 * j;
            const uint32_t vBH = smB + AT_VH + ((kb + lrT) * AT_STRIDE + lcT) * 2;
            const uint32_t vBL = smB + AT_VL + ((kb + lrT) * AT_STRIDE + lcT) * 2;
            #pragma unroll
            for (int ng = 0; ng < 16; ng++) {
                uint32_t vh4[4], vl4[4];
                LDSM4T(vh4, vBH + ng * 32);
                LDSM4T(vl4, vBL + ng * 32);
                MMA16816(o[2*ng+0], aPh[j], vh4[0], vh4[2]);
                MMA16816(o[2*ng+0], aPh[j], vl4[0], vl4[2]);
                MMA16816(o[2*ng+0], aPl[j], vh4[0], vh4[2]);
                MMA16816(o[2*ng+1], aPh[j], vh4[1], vh4[3]);
                MMA16816(o[2*ng+1], aPh[j], vl4[1], vl4[3]);
                MMA16816(o[2*ng+1], aPl[j], vh4[1], vh4[3]);
            }
        }
        __syncthreads();
    }

    rs0 += __shfl_xor_sync(0xffffffffu, rs0, 1);
    rs0 += __shfl_xor_sync(0xffffffffu, rs0, 2);
    rs1 += __shfl_xor_sync(0xffffffffu, rs1, 1);
    rs1 += __shfl_xor_sync(0xffffffffu, rs1, 2);

    float* scratch = (float*)(sm + AT_KH);
    if (ngrp == 1) {
        if (qd == 0) {
            rsumS[m0 + gid]     = rs0;
            rsumS[m0 + gid + 8] = rs1;
        }
        #pragma unroll
        for (int nt = 0; nt < 32; nt++) {
            const int colb = 8 * nt + 2 * qd;
            scratch[(m0 + gid)     * 256 + colb]     = o[nt][0];
            scratch[(m0 + gid)     * 256 + colb + 1] = o[nt][1];
            scratch[(m0 + gid + 8) * 256 + colb]     = o[nt][2];
            scratch[(m0 + gid + 8) * 256 + colb + 1] = o[nt][3];
        }
    }
    __syncthreads();
    if (ngrp == 0) {
        const float inv0 = 1.0f / (rs0 + rsumS[m0 + gid]);
        const float inv1 = 1.0f / (rs1 + rsumS[m0 + gid + 8]);
        const int row0 = s0 + m0 + gid, row1 = row0 + 8;
        #pragma unroll
        for (int nt = 0; nt < 32; nt++) {
            const int colb = 8 * nt + 2 * qd;
            const float v0 = (o[nt][0] + scratch[(m0+gid)  *256 + colb    ]) * inv0;
            const float v1 = (o[nt][1] + scratch[(m0+gid)  *256 + colb + 1]) * inv0;
            const float v2 = (o[nt][2] + scratch[(m0+gid+8)*256 + colb    ]) * inv1;
            const float v3 = (o[nt][3] + scratch[(m0+gid+8)*256 + colb + 1]) * inv1;
            const __nv_bfloat16 h0 = __float2bfloat16(v0);
            const __nv_bfloat16 h1 = __float2bfloat16(v1);
            const __nv_bfloat16 h2 = __float2bfloat16(v2);
            const __nv_bfloat16 h3 = __float2bfloat16(v3);
            const uint32_t hi01 = pack_bf16x2(h0, h1);
            const uint32_t hi23 = pack_bf16x2(h2, h3);
            const uint32_t lo01 = pack_bf16x2(
                __float2bfloat16(v0 - __bfloat162float(h0)),
                __float2bfloat16(v1 - __bfloat162float(h1)));
            const uint32_t lo23 = pack_bf16x2(
                __float2bfloat16(v2 - __bfloat162float(h2)),
                __float2bfloat16(v3 - __bfloat162float(h3)));
            *(uint32_t*)&g_atth[(size_t)row0 * HIDDEN + h * DH + colb] = hi01;
            *(uint32_t*)&g_attl[(size_t)row0 * HIDDEN + h * DH + colb] = lo01;
            *(uint32_t*)&g_atth[(size_t)row1 * HIDDEN + h * DH + colb] = hi23;
            *(uint32_t*)&g_attl[(size_t)row1 * HIDDEN + h * DH + colb] = lo23;
        }
    }
}

/* ------------------------------- launch ---------------------------------- */
extern "C" void kernel_launch(void* const* d_in, const int* in_sizes, int n_in,
                              void* d_out, int out_size)
{
    const float* x   = (const float*)d_in[0];
    const float* fc  = (const float*)d_in[1];
    const float* fs  = (const float*)d_in[2];
    const float* WAq = (const float*)d_in[3];
    const float* WAk = (const float*)d_in[4];
    const float* WAv = (const float*)d_in[5];
    const float* WBq = (const float*)d_in[6];
    const float* WBk = (const float*)d_in[7];
    const float* WBv = (const float*)d_in[8];
    const float* Wo  = (const float*)d_in[9];
    const float* qw  = (const float*)d_in[10];
    const float* kw  = (const float*)d_in[11];
    const float* kcA = (const float*)d_in[12];
    const float* kcB = (const float*)d_in[13];
    const float* vcA = (const float*)d_in[14];
    const float* vcB = (const float*)d_in[15];
    const int*   idx = (const int*)d_in[16];
    float* out = (float*)d_out;

    float *pProj;
    __nv_bfloat16 *pxh, *pxl, *pWch, *pWcl, *pWoh, *pWol, *patth, *pattl;
    cudaGetSymbolAddress((void**)&pProj, g_proj);
    cudaGetSymbolAddress((void**)&pxh,   g_xh);
    cudaGetSymbolAddress((void**)&pxl,   g_xl);
    cudaGetSymbolAddress((void**)&pWch,  g_Wcat_h);
    cudaGetSymbolAddress((void**)&pWcl,  g_Wcat_l);
    cudaGetSymbolAddress((void**)&pWoh,  g_Wo_h);
    cudaGetSymbolAddress((void**)&pWol,  g_Wo_l);
    cudaGetSymbolAddress((void**)&patth, g_atth);
    cudaGetSymbolAddress((void**)&pattl, g_attl);

    cudaFuncSetAttribute(attn_kernel,
                         cudaFuncAttributeMaxDynamicSharedMemorySize,
                         ATTN_SMEM_BYTES);

    const dim3 blk(256);
    const int MB = S_LEN / 128;   /* 32 */

    /* prologue: 5 launches, so the merged projection GEMM is launch #6
       (the one ncu -s 5 -c 1 profiles) */
    split_kernel<<<2048, blk>>>(x,  pxh, pxl, S_LEN * HIDDEN);          /* 1 */
    prepw_kernel<<<2048, blk>>>(WAq, WAk, WAv, WBq, WBk, WBv, 0, 1344); /* 2 */
    prepw_kernel<<<2048, blk>>>(WAq, WAk, WAv, WBq, WBk, WBv, 1344, 1344); /* 3 */
    split_kernel<<<2048, blk>>>(Wo, pWoh, pWol, HIDDEN * HIDDEN);       /* 4 */
    copy_caches_kernel<<<(S_LEN * 512 + 255) / 256, blk>>>(kcA, kcB, vcA, vcB); /* 5 */

    /* merged projection GEMM: all of A_q|A_k|A_v|B_q|B_k|B_v in one launch */
    hgemm_kernel<<<dim3(NPROJ / 128, MB), blk>>>(pxh, pxl, pWch, pWcl,
                                                 pProj, NPROJ, HIDDEN);  /* 6 */

    rope_q_kernel<<<S_LEN, 128>>>(fc, fs);
    scatter_kernel<<<S_LEN, blk>>>(idx, fc, fs);
    contract_q_kernel <<<S_LEN, blk>>>(qw);
    contract_kv_kernel<<<S_LEN, blk>>>(kw);

    attn_kernel<<<dim3(S_LEN / 64, NH), blk, ATTN_SMEM_BYTES>>>(idx);

    hgemm_kernel<<<dim3(16, MB), blk>>>(patth, pattl, pWoh, pWol, out,
                                        HIDDEN, HIDDEN);
}

// round 15
// speedup vs baseline: 8.2865x; 1.0171x over previous
#include <cuda_runtime.h>
#include <cuda_bf16.h>
#include <math.h>
#include <stdint.h>

#define S_LEN   4096
#define HIDDEN  2048
#define NH      8
#define NKVH    4
#define DH      256
#define QR      6
#define KR      2
#define VR      2
#define WINDOW  1024
#define SOFTCAP 50.0f
#define SCALING 0.0625f     /* 256^-0.5 */
#define EPSV    1e-6f

/* merged projection layout: [Aqkv(128) | Bq(1536) | Bk(512) | Bv(512)] */
#define NPROJ   2688
#define OFF_A   0
#define OFF_BQ  128
#define OFF_BK  1664
#define OFF_BV  2176

/* ---------------- scratch (device globals; no allocation allowed) -------- */
__device__ float g_proj[S_LEN * NPROJ];

/* bf16 split operands */
__device__ __nv_bfloat16 g_xh [S_LEN * HIDDEN];
__device__ __nv_bfloat16 g_xl [S_LEN * HIDDEN];
__device__ __nv_bfloat16 g_Wcat_h[NPROJ * HIDDEN];
__device__ __nv_bfloat16 g_Wcat_l[NPROJ * HIDDEN];
__device__ __nv_bfloat16 g_Wo_h[HIDDEN * HIDDEN];
__device__ __nv_bfloat16 g_Wo_l[HIDDEN * HIDDEN];

/* bf16 split q/k/v and attention output */
__device__ __nv_bfloat16 g_qh[S_LEN * NH * DH];
__device__ __nv_bfloat16 g_ql[S_LEN * NH * DH];
__device__ __nv_bfloat16 g_kh[S_LEN * NKVH * DH];
__device__ __nv_bfloat16 g_kl[S_LEN * NKVH * DH];
__device__ __nv_bfloat16 g_vh[S_LEN * NKVH * DH];
__device__ __nv_bfloat16 g_vl[S_LEN * NKVH * DH];
__device__ __nv_bfloat16 g_atth[S_LEN * HIDDEN];
__device__ __nv_bfloat16 g_attl[S_LEN * HIDDEN];

/* ---------------- fp32 -> (bf16 hi, bf16 lo) split ----------------------- */
__global__ void split_kernel(const float* __restrict__ in,
                             __nv_bfloat16* __restrict__ hi,
                             __nv_bfloat16* __restrict__ lo, int n)
{
    for (int i = blockIdx.x * 256 + threadIdx.x; i < n; i += gridDim.x * 256) {
        const float a = in[i];
        const __nv_bfloat16 h = __float2bfloat16(a);
        hi[i] = h;
        lo[i] = __float2bfloat16(a - __bfloat162float(h));
    }
}

/* ----- build concatenated weight [WAq|WAk|WAv|0 ... WBq | WBk | WBv] ----- */
__global__ void prepw_kernel(const float* __restrict__ WAq,
                             const float* __restrict__ WAk,
                             const float* __restrict__ WAv,
                             const float* __restrict__ WBq,
                             const float* __restrict__ WBk,
                             const float* __restrict__ WBv)
{
    const int total = NPROJ * HIDDEN;
    for (int i = blockIdx.x * 256 + threadIdx.x; i < total;
         i += gridDim.x * 256) {
        const int row = i >> 11, col = i & 2047;
        float v = 0.f;
        if (row < 48)            v = WAq[row * HIDDEN + col];
        else if (row < 56)       v = WAk[(row - 48) * HIDDEN + col];
        else if (row < 64)       v = WAv[(row - 56) * HIDDEN + col];
        else if (row < OFF_BQ)   v = 0.f;
        else if (row < OFF_BK)   v = WBq[(row - OFF_BQ) * HIDDEN + col];
        else if (row < OFF_BV)   v = WBk[(row - OFF_BK) * HIDDEN + col];
        else                     v = WBv[(row - OFF_BV) * HIDDEN + col];
        const __nv_bfloat16 h = __float2bfloat16(v);
        g_Wcat_h[row * HIDDEN + col] = h;
        g_Wcat_l[row * HIDDEN + col] =
            __float2bfloat16(v - __bfloat162float(h));
    }
}

/* ---------------- MMA / ldmatrix macros ---------------------------------- */
#define LDSM4(d, a) \
    asm volatile("ldmatrix.sync.aligned.m8n8.x4.shared.b16 {%0,%1,%2,%3}, [%4];" \
        : "=r"(d[0]), "=r"(d[1]), "=r"(d[2]), "=r"(d[3]) : "r"(a))

#define LDSM4T(d, a) \
    asm volatile("ldmatrix.sync.aligned.m8n8.x4.trans.shared.b16 {%0,%1,%2,%3}, [%4];" \
        : "=r"(d[0]), "=r"(d[1]), "=r"(d[2]), "=r"(d[3]) : "r"(a))

#define MMA16816(c, a, b0, b1) \
    asm volatile("mma.sync.aligned.m16n8k16.row.col.f32.bf16.bf16.f32 " \
        "{%0,%1,%2,%3}, {%4,%5,%6,%7}, {%8,%9}, {%0,%1,%2,%3};" \
        : "+f"(c[0]), "+f"(c[1]), "+f"(c[2]), "+f"(c[3]) \
        : "r"(a[0]), "r"(a[1]), "r"(a[2]), "r"(a[3]), "r"(b0), "r"(b1))

/* ---------------- HMMA split-bf16 GEMM: C[M,N] = A @ W^T ------------------ */
__global__ __launch_bounds__(256) void hgemm_kernel(
    const __nv_bfloat16* __restrict__ Ah, const __nv_bfloat16* __restrict__ Al,
    const __nv_bfloat16* __restrict__ Wh, const __nv_bfloat16* __restrict__ Wl,
    float* __restrict__ C, int N, int K)
{
    __shared__ __align__(16) __nv_bfloat16 sm[2][4][128 * 24];
    const int tid  = threadIdx.x;
    const int m0   = blockIdx.y * 128, n0 = blockIdx.x * 128;
    const int warp = tid >> 5, lane = tid & 31;
    const int wm   = (warp & 1) * 64, wn = (warp >> 1) * 32;

    const int ldr = tid >> 1, lds8 = (tid & 1) * 8;
    const __nv_bfloat16* gAh = Ah + (size_t)(m0 + ldr) * K + lds8;
    const __nv_bfloat16* gAl = Al + (size_t)(m0 + ldr) * K + lds8;
    const __nv_bfloat16* gWh = Wh + (size_t)(n0 + ldr) * K + lds8;
    const __nv_bfloat16* gWl = Wl + (size_t)(n0 + ldr) * K + lds8;
    const int stoff = ldr * 24 + lds8;

    const int r8   = lane & 7, tq = lane >> 3;
    const int lrow = (tq & 1) * 8 + r8;
    const int lcol = (tq >> 1) * 8;
    const uint32_t smBase = (uint32_t)__cvta_generic_to_shared(&sm[0][0][0]);
    const uint32_t aoff = ((wm + lrow) * 24 + lcol) * 2;
    const uint32_t boff = ((wn + lrow) * 24 + lcol) * 2;

    float c[4][4][4];
    #pragma unroll
    for (int mt = 0; mt < 4; mt++)
        #pragma unroll
        for (int nt = 0; nt < 4; nt++)
            #pragma unroll
            for (int f = 0; f < 4; f++) c[mt][nt][f] = 0.f;

    {
        uint4 va = *(const uint4*)gAh;
        uint4 vb = *(const uint4*)gAl;
        uint4 vc = *(const uint4*)gWh;
        uint4 vd = *(const uint4*)gWl;
        *(uint4*)&sm[0][0][stoff] = va;
        *(uint4*)&sm[0][1][stoff] = vb;
        *(uint4*)&sm[0][2][stoff] = vc;
        *(uint4*)&sm[0][3][stoff] = vd;
    }

    const int NS = K >> 4;
    for (int ks = 0; ks < NS; ks++) {
        __syncthreads();
        const int buf = ks & 1;
        if (ks + 1 < NS) {
            const int ko = (ks + 1) << 4;
            uint4 va = *(const uint4*)(gAh + ko);
            uint4 vb = *(const uint4*)(gAl + ko);
            uint4 vc = *(const uint4*)(gWh + ko);
            uint4 vd = *(const uint4*)(gWl + ko);
            const int nb = buf ^ 1;
            *(uint4*)&sm[nb][0][stoff] = va;
            *(uint4*)&sm[nb][1][stoff] = vb;
            *(uint4*)&sm[nb][2][stoff] = vc;
            *(uint4*)&sm[nb][3][stoff] = vd;
        }
        const uint32_t base = smBase + (uint32_t)buf * (4 * 3072 * 2);
        uint32_t ah[4][4], al[4][4], bh[2][4], bl[2][4];
        #pragma unroll
        for (int mt = 0; mt < 4; mt++) {
            LDSM4(ah[mt], base + 0 * 6144 + aoff + mt * 768);
            LDSM4(al[mt], base + 1 * 6144 + aoff + mt * 768);
        }
        #pragma unroll
        for (int p = 0; p < 2; p++) {
            LDSM4(bh[p], base + 2 * 6144 + boff + p * 768);
            LDSM4(bl[p], base + 3 * 6144 + boff + p * 768);
        }
        #pragma unroll
        for (int mt = 0; mt < 4; mt++)
            #pragma unroll
            for (int nt = 0; nt < 4; nt++) {
                const int p = nt >> 1, q = nt & 1;
                MMA16816(c[mt][nt], ah[mt], bh[p][q], bh[p][q + 2]);
                MMA16816(c[mt][nt], ah[mt], bl[p][q], bl[p][q + 2]);
                MMA16816(c[mt][nt], al[mt], bh[p][q], bh[p][q + 2]);
            }
    }

    const int gid = lane >> 2, tg = lane & 3;
    #pragma unroll
    for (int mt = 0; mt < 4; mt++)
        #pragma unroll
        for (int nt = 0; nt < 4; nt++) {
            const int row = m0 + wm + mt * 16 + gid;
            const int col = n0 + wn + nt * 8 + tg * 2;
            float2 v0 = make_float2(c[mt][nt][0], c[mt][nt][1]);
            float2 v1 = make_float2(c[mt][nt][2], c[mt][nt][3]);
            *(float2*)&C[(size_t)row * N + col]       = v0;
            *(float2*)&C[(size_t)(row + 8) * N + col] = v1;
        }
}

/* -------- q = RMSNorm(sum_r Aq*rope(Bq)/QR)*(1+qw)*SCALING -> bf16 -------
 * RoPE fused via shfl: lanes d and d^1 exchange pair partners.            */
__global__ void contract_q_kernel(const float* __restrict__ fc,
                                  const float* __restrict__ fs,
                                  const float* __restrict__ qw)
{
    const int s = blockIdx.x;
    const int d = threadIdx.x;                 /* 256 */
    __shared__ float a[48];
    __shared__ float wsum[8][8];
    const float* prow = &g_proj[(size_t)s * NPROJ];
    if (d < 48) a[d] = prow[d];
    __syncthreads();

    const float c  = fc[s * 128 + (d >> 1)];
    const float sn = fs[s * 128 + (d >> 1)];

    float bq[QR];
    #pragma unroll
    for (int r = 0; r < QR; r++) {
        const float raw = prow[OFF_BQ + r * DH + d];
        const float prt = __shfl_xor_sync(0xffffffffu, raw, 1);
        /* even d: x1=raw, x2=prt -> x1*c - x2*sn ; odd d: x1=prt, x2=raw */
        bq[r] = (d & 1) ? (prt * sn + raw * c) : (raw * c - prt * sn);
    }

    float acc[NH];
    #pragma unroll
    for (int h = 0; h < NH; h++) {
        float v = 0.f;
        #pragma unroll
        for (int r = 0; r < QR; r++) v += a[h * QR + r] * bq[r];
        acc[h] = v * (1.0f / (float)QR);
    }
    const int lane = d & 31, warp = d >> 5;
    #pragma unroll
    for (int h = 0; h < NH; h++) {
        float v = acc[h] * acc[h];
        for (int o = 16; o > 0; o >>= 1) v += __shfl_xor_sync(0xffffffffu, v, o);
        if (lane == 0) wsum[h][warp] = v;
    }
    __syncthreads();
    const float w = 1.0f + qw[d];
    #pragma unroll
    for (int h = 0; h < NH; h++) {
        float tot = 0.f;
        #pragma unroll
        for (int i = 0; i < 8; i++) tot += wsum[h][i];
        const float rn = rsqrtf(tot * (1.0f / (float)DH) + EPSV);
        const float val = acc[h] * rn * w * SCALING;
        const __nv_bfloat16 hi = __float2bfloat16(val);
        g_qh[(s * NH + h) * DH + d] = hi;
        g_ql[(s * NH + h) * DH + d] =
            __float2bfloat16(val - __bfloat162float(hi));
    }
}

/* -------- fused scatter+contract_kv: read g_proj row s, rope k inline,
 * rmsnorm/scale, write bf16 k/v at row t = idx[s]. (kv_write_indices covers
 * all S rows, so the zero-initialized cache inputs never survive.)        */
__global__ void fusedkv_kernel(const int* __restrict__ idx,
                               const float* __restrict__ fc,
                               const float* __restrict__ fs,
                               const float* __restrict__ kw)
{
    const int s = blockIdx.x;
    const int d = threadIdx.x;                 /* 256 */
    const int t = idx[s];
    const float* prow = &g_proj[(size_t)s * NPROJ];

    __shared__ float a[16];                    /* [0:8)=kA, [8:16)=vA */
    __shared__ float wsum[4][8];
    if (d < 8)               a[d] = prow[48 + d];
    else if (d < 16)         a[d] = prow[56 + (d - 8)];
    __syncthreads();

    const float c  = fc[s * 128 + (d >> 1)];
    const float sn = fs[s * 128 + (d >> 1)];

    float kb0, kb1;
    {
        const float raw = prow[OFF_BK + d];
        const float prt = __shfl_xor_sync(0xffffffffu, raw, 1);
        kb0 = (d & 1) ? (prt * sn + raw * c) : (raw * c - prt * sn);
    }
    {
        const float raw = prow[OFF_BK + DH + d];
        const float prt = __shfl_xor_sync(0xffffffffu, raw, 1);
        kb1 = (d & 1) ? (prt * sn + raw * c) : (raw * c - prt * sn);
    }
    const float vb0 = prow[OFF_BV + d];
    const float vb1 = prow[OFF_BV + 256 + d];

    float kacc[NKVH], vacc[NKVH];
    #pragma unroll
    for (int kh = 0; kh < NKVH; kh++) {
        kacc[kh] = 0.5f * (a[kh * 2] * kb0 + a[kh * 2 + 1] * kb1);
        vacc[kh] = 0.5f * (a[8 + kh * 2] * vb0 + a[8 + kh * 2 + 1] * vb1);
    }
    const int lane = d & 31, warp = d >> 5;
    #pragma unroll
    for (int kh = 0; kh < NKVH; kh++) {
        float v = kacc[kh] * kacc[kh];
        for (int o = 16; o > 0; o >>= 1) v += __shfl_xor_sync(0xffffffffu, v, o);
        if (lane == 0) wsum[kh][warp] = v;
    }
    __syncthreads();
    const float w = 1.0f + kw[d];
    #pragma unroll
    for (int kh = 0; kh < NKVH; kh++) {
        float tot = 0.f;
        #pragma unroll
        for (int i = 0; i < 8; i++) tot += wsum[kh][i];
        const float rn = rsqrtf(tot * (1.0f / (float)DH) + EPSV);
        const float kv = kacc[kh] * rn * w;
        const float vv = vacc[kh];
        const __nv_bfloat16 khi = __float2bfloat16(kv);
        const __nv_bfloat16 vhi = __float2bfloat16(vv);
        const int o = (t * NKVH + kh) * DH + d;
        g_kh[o] = khi;
        g_kl[o] = __float2bfloat16(kv - __bfloat162float(khi));
        g_vh[o] = vhi;
        g_vl[o] = __float2bfloat16(vv - __bfloat162float(vhi));
    }
}

/* ---------------- MMA sliding-window softcapped attention ---------------- */
#define AT_STRIDE 264
#define AT_TILE_B (64 * AT_STRIDE * 2)
#define AT_QH 0
#define AT_QL (1 * AT_TILE_B)
#define AT_KH (2 * AT_TILE_B)
#define AT_KL (3 * AT_TILE_B)
#define AT_VH (4 * AT_TILE_B)
#define AT_VL (5 * AT_TILE_B)
#define AT_QPOS (6 * AT_TILE_B)
#define AT_RSUM (AT_QPOS + 256)
#define ATTN_SMEM_BYTES (AT_RSUM + 256)

__device__ __forceinline__ uint32_t pack_bf16x2(__nv_bfloat16 lo, __nv_bfloat16 hi)
{
    return ((uint32_t)__bfloat16_as_ushort(hi) << 16) |
           (uint32_t)__bfloat16_as_ushort(lo);
}

__global__ __launch_bounds__(256) void attn_kernel(const int* __restrict__ idx)
{
    extern __shared__ char sm[];
    const int s0  = blockIdx.x * 64;
    const int h   = blockIdx.y;
    const int kvh = h >> 1;
    const int tid = threadIdx.x, warp = tid >> 5, lane = tid & 31;
    const int mgrp = warp & 3, ngrp = warp >> 2;
    const int m0 = mgrp * 16, n0 = ngrp * 32;
    const int r8 = lane & 7, tq = lane >> 3;
    const int lrA = (tq & 1) * 8 + r8, lcA = (tq >> 1) * 8;
    const int lrT = (tq >> 1) * 8 + r8, lcT = (tq & 1) * 8;
    const int gid = lane >> 2, qd = lane & 3;

    const uint32_t smB = (uint32_t)__cvta_generic_to_shared(sm);
    int*   qpos  = (int*)(sm + AT_QPOS);
    float* rsumS = (float*)(sm + AT_RSUM);

    #pragma unroll
    for (int c = 0; c < 8; c++) {
        const int i4 = tid + c * 256;
        const int row = i4 >> 5, col = (i4 & 31) * 8;
        const size_t g = ((size_t)(s0 + row) * NH + h) * DH + col;
        const int so = (row * AT_STRIDE + col) * 2;
        *(uint4*)(sm + AT_QH + so) = *(const uint4*)(g_qh + g);
        *(uint4*)(sm + AT_QL + so) = *(const uint4*)(g_ql + g);
    }
    if (tid < 64) qpos[tid] = idx[s0 + tid];

    float o[32][4];
    #pragma unroll
    for (int nt = 0; nt < 32; nt++)
        #pragma unroll
        for (int f = 0; f < 4; f++) o[nt][f] = 0.f;
    float rs0 = 0.f, rs1 = 0.f;

    const uint32_t aQH  = smB + AT_QH + ((m0 + lrA) * AT_STRIDE + lcA) * 2;
    const uint32_t aQL  = smB + AT_QL + ((m0 + lrA) * AT_STRIDE + lcA) * 2;
    const uint32_t bK0H = smB + AT_KH + ((n0 + lrA) * AT_STRIDE + lcA) * 2;
    const uint32_t bK0L = smB + AT_KL + ((n0 + lrA) * AT_STRIDE + lcA) * 2;
    const uint32_t bK1H = bK0H + 16 * AT_STRIDE * 2;
    const uint32_t bK1L = bK0L + 16 * AT_STRIDE * 2;

    int tlo = s0 - (WINDOW - 1);
    if (tlo < 0) tlo = 0;
    tlo &= ~63;

    for (int t0 = tlo; t0 < s0 + 64; t0 += 64) {
        #pragma unroll
        for (int c = 0; c < 8; c++) {
            const int i4 = tid + c * 256;
            const int row = i4 >> 5, col = (i4 & 31) * 8;
            const size_t g = ((size_t)(t0 + row) * NKVH + kvh) * DH + col;
            const int so = (row * AT_STRIDE + col) * 2;
            *(uint4*)(sm + AT_KH + so) = *(const uint4*)(g_kh + g);
            *(uint4*)(sm + AT_KL + so) = *(const uint4*)(g_kl + g);
            *(uint4*)(sm + AT_VH + so) = *(const uint4*)(g_vh + g);
            *(uint4*)(sm + AT_VL + so) = *(const uint4*)(g_vl + g);
        }
        __syncthreads();

        float sc[4][4];
        #pragma unroll
        for (int nt = 0; nt < 4; nt++)
            #pragma unroll
            for (int f = 0; f < 4; f++) sc[nt][f] = 0.f;

        #pragma unroll
        for (int ks = 0; ks < 16; ks++) {
            const uint32_t ko = ks * 32;
            uint32_t aH[4], aL[4], b0H[4], b0L[4], b1H[4], b1L[4];
            LDSM4(aH, aQH + ko);
            LDSM4(aL, aQL + ko);
            LDSM4(b0H, bK0H + ko);
            LDSM4(b0L, bK0L + ko);
            LDSM4(b1H, bK1H + ko);
            LDSM4(b1L, bK1L + ko);
            MMA16816(sc[0], aH, b0H[0], b0H[2]);
            MMA16816(sc[0], aH, b0L[0], b0L[2]);
            MMA16816(sc[0], aL, b0H[0], b0H[2]);
            MMA16816(sc[1], aH, b0H[1], b0H[3]);
            MMA16816(sc[1], aH, b0L[1], b0L[3]);
            MMA16816(sc[1], aL, b0H[1], b0H[3]);
            MMA16816(sc[2], aH, b1H[0], b1H[2]);
            MMA16816(sc[2], aH, b1L[0], b1L[2]);
            MMA16816(sc[2], aL, b1H[0], b1H[2]);
            MMA16816(sc[3], aH, b1H[1], b1H[3]);
            MMA16816(sc[3], aH, b1L[1], b1L[3]);
            MMA16816(sc[3], aL, b1H[1], b1H[3]);
        }

        const int qp0 = qpos[m0 + gid], qp1 = qpos[m0 + gid + 8];
        uint32_t aPh[2][4], aPl[2][4];
        #pragma unroll
        for (int nt = 0; nt < 4; nt++) {
            const int colb = n0 + 8 * nt + 2 * qd;
            const int kp0 = t0 + colb, kp1 = kp0 + 1;
            float p[4];
            {
                const float e = tanhf(sc[nt][0] * (1.0f/SOFTCAP)) * SOFTCAP;
                const int d = qp0 - kp0;
                p[0] = (d >= 0 && d < WINDOW) ? __expf(e - SOFTCAP) : 0.f;
            }
            {
                const float e = tanhf(sc[nt][1] * (1.0f/SOFTCAP)) * SOFTCAP;
                const int d = qp0 - kp1;
                p[1] = (d >= 0 && d < WINDOW) ? __expf(e - SOFTCAP) : 0.f;
            }
            {
                const float e = tanhf(sc[nt][2] * (1.0f/SOFTCAP)) * SOFTCAP;
                const int d = qp1 - kp0;
                p[2] = (d >= 0 && d < WINDOW) ? __expf(e - SOFTCAP) : 0.f;
            }
            {
                const float e = tanhf(sc[nt][3] * (1.0f/SOFTCAP)) * SOFTCAP;
                const int d = qp1 - kp1;
                p[3] = (d >= 0 && d < WINDOW) ? __expf(e - SOFTCAP) : 0.f;
            }
            rs0 += p[0] + p[1];
            rs1 += p[2] + p[3];
            const __nv_bfloat16 h0 = __float2bfloat16(p[0]);
            const __nv_bfloat16 h1 = __float2bfloat16(p[1]);
            const __nv_bfloat16 h2 = __float2bfloat16(p[2]);
            const __nv_bfloat16 h3 = __float2bfloat16(p[3]);
            const __nv_bfloat16 l0 = __float2bfloat16(p[0] - __bfloat162float(h0));
            const __nv_bfloat16 l1 = __float2bfloat16(p[1] - __bfloat162float(h1));
            const __nv_bfloat16 l2 = __float2bfloat16(p[2] - __bfloat162float(h2));
            const __nv_bfloat16 l3 = __float2bfloat16(p[3] - __bfloat162float(h3));
            const int j = nt >> 1, r = (nt & 1) * 2;
            aPh[j][r + 0] = pack_bf16x2(h0, h1);
            aPh[j][r + 1] = pack_bf16x2(h2, h3);
            aPl[j][r + 0] = pack_bf16x2(l0, l1);
            aPl[j][r + 1] = pack_bf16x2(l2, l3);
        }

        #pragma unroll
        for (int j = 0; j < 2; j++) {
            const int kb = n0 + 16 * j;
            const uint32_t vBH = smB + AT_VH + ((kb + lrT) * AT_STRIDE + lcT) * 2;
            const uint32_t vBL = smB + AT_VL + ((kb + lrT) * AT_STRIDE + lcT) * 2;
            #pragma unroll
            for (int ng = 0; ng < 16; ng++) {
                uint32_t vh4[4], vl4[4];
                LDSM4T(vh4, vBH + ng * 32);
                LDSM4T(vl4, vBL + ng * 32);
                MMA16816(o[2*ng+0], aPh[j], vh4[0], vh4[2]);
                MMA16816(o[2*ng+0], aPh[j], vl4[0], vl4[2]);
                MMA16816(o[2*ng+0], aPl[j], vh4[0], vh4[2]);
                MMA16816(o[2*ng+1], aPh[j], vh4[1], vh4[3]);
                MMA16816(o[2*ng+1], aPh[j], vl4[1], vl4[3]);
                MMA16816(o[2*ng+1], aPl[j], vh4[1], vh4[3]);
            }
        }
        __syncthreads();
    }

    rs0 += __shfl_xor_sync(0xffffffffu, rs0, 1);
    rs0 += __shfl_xor_sync(0xffffffffu, rs0, 2);
    rs1 += __shfl_xor_sync(0xffffffffu, rs1, 1);
    rs1 += __shfl_xor_sync(0xffffffffu, rs1, 2);

    float* scratch = (float*)(sm + AT_KH);
    if (ngrp == 1) {
        if (qd == 0) {
            rsumS[m0 + gid]     = rs0;
            rsumS[m0 + gid + 8] = rs1;
        }
        #pragma unroll
        for (int nt = 0; nt < 32; nt++) {
            const int colb = 8 * nt + 2 * qd;
            scratch[(m0 + gid)     * 256 + colb]     = o[nt][0];
            scratch[(m0 + gid)     * 256 + colb + 1] = o[nt][1];
            scratch[(m0 + gid + 8) * 256 + colb]     = o[nt][2];
            scratch[(m0 + gid + 8) * 256 + colb + 1] = o[nt][3];
        }
    }
    __syncthreads();
    if (ngrp == 0) {
        const float inv0 = 1.0f / (rs0 + rsumS[m0 + gid]);
        const float inv1 = 1.0f / (rs1 + rsumS[m0 + gid + 8]);
        const int row0 = s0 + m0 + gid, row1 = row0 + 8;
        #pragma unroll
        for (int nt = 0; nt < 32; nt++) {
            const int colb = 8 * nt + 2 * qd;
            const float v0 = (o[nt][0] + scratch[(m0+gid)  *256 + colb    ]) * inv0;
            const float v1 = (o[nt][1] + scratch[(m0+gid)  *256 + colb + 1]) * inv0;
            const float v2 = (o[nt][2] + scratch[(m0+gid+8)*256 + colb    ]) * inv1;
            const float v3 = (o[nt][3] + scratch[(m0+gid+8)*256 + colb + 1]) * inv1;
            const __nv_bfloat16 h0 = __float2bfloat16(v0);
            const __nv_bfloat16 h1 = __float2bfloat16(v1);
            const __nv_bfloat16 h2 = __float2bfloat16(v2);
            const __nv_bfloat16 h3 = __float2bfloat16(v3);
            const uint32_t hi01 = pack_bf16x2(h0, h1);
            const uint32_t hi23 = pack_bf16x2(h2, h3);
            const uint32_t lo01 = pack_bf16x2(
                __float2bfloat16(v0 - __bfloat162float(h0)),
                __float2bfloat16(v1 - __bfloat162float(h1)));
            const uint32_t lo23 = pack_bf16x2(
                __float2bfloat16(v2 - __bfloat162float(h2)),
                __float2bfloat16(v3 - __bfloat162float(h3)));
            *(uint32_t*)&g_atth[(size_t)row0 * HIDDEN + h * DH + colb] = hi01;
            *(uint32_t*)&g_attl[(size_t)row0 * HIDDEN + h * DH + colb] = lo01;
            *(uint32_t*)&g_atth[(size_t)row1 * HIDDEN + h * DH + colb] = hi23;
            *(uint32_t*)&g_attl[(size_t)row1 * HIDDEN + h * DH + colb] = lo23;
        }
    }
}

/* ------------------------------- launch ---------------------------------- */
extern "C" void kernel_launch(void* const* d_in, const int* in_sizes, int n_in,
                              void* d_out, int out_size)
{
    const float* x   = (const float*)d_in[0];
    const float* fc  = (const float*)d_in[1];
    const float* fs  = (const float*)d_in[2];
    const float* WAq = (const float*)d_in[3];
    const float* WAk = (const float*)d_in[4];
    const float* WAv = (const float*)d_in[5];
    const float* WBq = (const float*)d_in[6];
    const float* WBk = (const float*)d_in[7];
    const float* WBv = (const float*)d_in[8];
    const float* Wo  = (const float*)d_in[9];
    const float* qw  = (const float*)d_in[10];
    const float* kw  = (const float*)d_in[11];
    const int*   idx = (const int*)d_in[16];
    float* out = (float*)d_out;

    float *pProj;
    __nv_bfloat16 *pxh, *pxl, *pWch, *pWcl, *pWoh, *pWol, *patth, *pattl;
    cudaGetSymbolAddress((void**)&pProj, g_proj);
    cudaGetSymbolAddress((void**)&pxh,   g_xh);
    cudaGetSymbolAddress((void**)&pxl,   g_xl);
    cudaGetSymbolAddress((void**)&pWch,  g_Wcat_h);
    cudaGetSymbolAddress((void**)&pWcl,  g_Wcat_l);
    cudaGetSymbolAddress((void**)&pWoh,  g_Wo_h);
    cudaGetSymbolAddress((void**)&pWol,  g_Wo_l);
    cudaGetSymbolAddress((void**)&patth, g_atth);
    cudaGetSymbolAddress((void**)&pattl, g_attl);

    cudaFuncSetAttribute(attn_kernel,
                         cudaFuncAttributeMaxDynamicSharedMemorySize,
                         ATTN_SMEM_BYTES);

    const dim3 blk(256);
    const int MB = S_LEN / 128;   /* 32 */

    /* prologue (elementwise) */
    split_kernel<<<2048, blk>>>(x,  pxh, pxl, S_LEN * HIDDEN);
    prepw_kernel<<<4096, blk>>>(WAq, WAk, WAv, WBq, WBk, WBv);
    split_kernel<<<2048, blk>>>(Wo, pWoh, pWol, HIDDEN * HIDDEN);

    /* merged projection GEMM */
    hgemm_kernel<<<dim3(NPROJ / 128, MB), blk>>>(pxh, pxl, pWch, pWcl,
                                                 pProj, NPROJ, HIDDEN);

    /* fused rope+contract (q) and scatter+rope+contract (k,v) */
    contract_q_kernel<<<S_LEN, blk>>>(fc, fs, qw);
    fusedkv_kernel<<<S_LEN, blk>>>(idx, fc, fs, kw);

    /* attention (tensor cores) */
    attn_kernel<<<dim3(S_LEN / 64, NH), blk, ATTN_SMEM_BYTES>>>(idx);

    /* output projection (tensor cores) */
    hgemm_kernel<<<dim3(16, MB), blk>>>(patth, pattl, pWoh, pWol, out,
                                        HIDDEN, HIDDEN);
}